// round 1
// baseline (speedup 1.0000x reference)
#include <cuda_runtime.h>
#include <math.h>

#define T_TOKENS 4096
#define D_MODEL  1024
#define N_EXP    8
#define F_DIM    2048
#define LN_EPS   1e-5f
#define MAXP     4096   // max tokens per expert bucket

#define BM 128
#define BN 128
#define BK 8

// ---- scratch (device globals; no allocations allowed) ----
__device__ int   g_counts[N_EXP];
__device__ int   g_tok[N_EXP * MAXP];
__device__ float g_wt[N_EXP * MAXP];
__device__ int   g_slot[T_TOKENS * 2];
__device__ __align__(16) float g_H[(size_t)N_EXP * MAXP * F_DIM];   // 256 MB
__device__ __align__(16) float g_O[(size_t)N_EXP * MAXP * D_MODEL]; // 128 MB

// ---------------------------------------------------------------------------
__global__ void init_kernel() {
    if (threadIdx.x < N_EXP) g_counts[threadIdx.x] = 0;
}

// ---------------------------------------------------------------------------
// Gating: one warp per token. Computes 8 logits, top-2, softmax over the two,
// appends token into the two expert buckets, records slots for combine.
__global__ void gating_kernel(const float* __restrict__ x,
                              const float* __restrict__ Wg,
                              const float* __restrict__ bg) {
    int warp = threadIdx.x >> 5;
    int lane = threadIdx.x & 31;
    int t = blockIdx.x * 8 + warp;
    if (t >= T_TOKENS) return;

    float acc[8];
#pragma unroll
    for (int e = 0; e < 8; e++) acc[e] = 0.f;

    const float* xr = x + (size_t)t * D_MODEL;
    for (int k = lane; k < D_MODEL; k += 32) {
        float xv = xr[k];
        float4 w0 = *(const float4*)(Wg + (size_t)k * 8);
        float4 w1 = *(const float4*)(Wg + (size_t)k * 8 + 4);
        acc[0] += xv * w0.x; acc[1] += xv * w0.y;
        acc[2] += xv * w0.z; acc[3] += xv * w0.w;
        acc[4] += xv * w1.x; acc[5] += xv * w1.y;
        acc[6] += xv * w1.z; acc[7] += xv * w1.w;
    }
#pragma unroll
    for (int e = 0; e < 8; e++) {
#pragma unroll
        for (int off = 16; off > 0; off >>= 1)
            acc[e] += __shfl_down_sync(0xffffffffu, acc[e], off);
    }

    if (lane == 0) {
        float v[8];
#pragma unroll
        for (int e = 0; e < 8; e++) v[e] = acc[e] + bg[e];
        int b0 = 0; float m0 = v[0];
#pragma unroll
        for (int e = 1; e < 8; e++) if (v[e] > m0) { m0 = v[e]; b0 = e; }
        int b1i = (b0 == 0) ? 1 : 0; float m1 = v[b1i];
#pragma unroll
        for (int e = 0; e < 8; e++)
            if (e != b0 && v[e] > m1) { m1 = v[e]; b1i = e; }

        float ex = expf(m1 - m0);
        float s  = 1.0f + ex;
        float w0 = 1.0f / s;
        float w1 = ex / s;

        int p0 = atomicAdd(&g_counts[b0], 1);
        g_tok[b0 * MAXP + p0] = t;
        g_wt [b0 * MAXP + p0] = w0;
        g_slot[t * 2 + 0] = b0 * MAXP + p0;

        int p1 = atomicAdd(&g_counts[b1i], 1);
        g_tok[b1i * MAXP + p1] = t;
        g_wt [b1i * MAXP + p1] = w1;
        g_slot[t * 2 + 1] = b1i * MAXP + p1;
    }
}

// ---------------------------------------------------------------------------
// GEMM1: per expert e, H[slot, 0:F] = relu( X[tok[slot], 0:D] @ W1[e] + b1[e] )
// Block tile 128x128, K-step 8, 256 threads, 8x8 per-thread micro-tile.
__global__ void __launch_bounds__(256, 2)
gemm1_kernel(const float* __restrict__ x,
             const float* __restrict__ W1,
             const float* __restrict__ b1) {
    int e   = blockIdx.z;
    int cnt = g_counts[e];
    int m0  = blockIdx.y * BM;
    if (m0 >= cnt) return;
    int n0  = blockIdx.x * BN;

    const float* Bw = W1 + (size_t)e * D_MODEL * F_DIM + n0;

    __shared__ __align__(16) float As[BK][BM + 4];
    __shared__ __align__(16) float Bs[BK][BN];

    int tid = threadIdx.x;
    int am  = tid >> 1;
    int ak  = (tid & 1) * 4;
    int aidx = m0 + am; if (aidx >= cnt) aidx = cnt - 1;
    const float* Arow = x + (size_t)g_tok[e * MAXP + aidx] * D_MODEL + ak;

    int bn = (tid & 31) * 4;
    int bk = tid >> 5;
    const float* Bp = Bw + (size_t)bk * F_DIM + bn;

    int tx = tid & 15, ty = tid >> 4;

    float acc[8][8];
#pragma unroll
    for (int i = 0; i < 8; i++)
#pragma unroll
        for (int j = 0; j < 8; j++) acc[i][j] = 0.f;

    for (int k0 = 0; k0 < D_MODEL; k0 += BK) {
        float4 av = *(const float4*)(Arow + k0);
        As[ak + 0][am] = av.x; As[ak + 1][am] = av.y;
        As[ak + 2][am] = av.z; As[ak + 3][am] = av.w;
        *(float4*)&Bs[bk][bn] = *(const float4*)(Bp + (size_t)k0 * F_DIM);
        __syncthreads();
#pragma unroll
        for (int kk = 0; kk < BK; kk++) {
            float a[8], b[8];
            *(float4*)(a)     = *(const float4*)&As[kk][ty * 8];
            *(float4*)(a + 4) = *(const float4*)&As[kk][ty * 8 + 4];
            *(float4*)(b)     = *(const float4*)&Bs[kk][tx * 8];
            *(float4*)(b + 4) = *(const float4*)&Bs[kk][tx * 8 + 4];
#pragma unroll
            for (int i = 0; i < 8; i++)
#pragma unroll
                for (int j = 0; j < 8; j++) acc[i][j] += a[i] * b[j];
        }
        __syncthreads();
    }

    float bb[8];
#pragma unroll
    for (int j = 0; j < 8; j++) bb[j] = b1[e * F_DIM + n0 + tx * 8 + j];

#pragma unroll
    for (int i = 0; i < 8; i++) {
        int row = m0 + ty * 8 + i;
        if (row < cnt) {
            float* Hr = g_H + ((size_t)e * MAXP + row) * F_DIM + n0 + tx * 8;
            float4 o0, o1;
            o0.x = fmaxf(acc[i][0] + bb[0], 0.f);
            o0.y = fmaxf(acc[i][1] + bb[1], 0.f);
            o0.z = fmaxf(acc[i][2] + bb[2], 0.f);
            o0.w = fmaxf(acc[i][3] + bb[3], 0.f);
            o1.x = fmaxf(acc[i][4] + bb[4], 0.f);
            o1.y = fmaxf(acc[i][5] + bb[5], 0.f);
            o1.z = fmaxf(acc[i][6] + bb[6], 0.f);
            o1.w = fmaxf(acc[i][7] + bb[7], 0.f);
            *(float4*)(Hr)     = o0;
            *(float4*)(Hr + 4) = o1;
        }
    }
}

// ---------------------------------------------------------------------------
// GEMM2: O[slot, 0:D] = wt[slot] * ( H[slot, 0:F] @ W2[e] + b2[e] )
__global__ void __launch_bounds__(256, 2)
gemm2_kernel(const float* __restrict__ W2,
             const float* __restrict__ b2) {
    int e   = blockIdx.z;
    int cnt = g_counts[e];
    int m0  = blockIdx.y * BM;
    if (m0 >= cnt) return;
    int n0  = blockIdx.x * BN;

    const float* Bw = W2 + (size_t)e * F_DIM * D_MODEL + n0;

    __shared__ __align__(16) float As[BK][BM + 4];
    __shared__ __align__(16) float Bs[BK][BN];

    int tid = threadIdx.x;
    int am  = tid >> 1;
    int ak  = (tid & 1) * 4;
    int aidx = m0 + am; if (aidx >= cnt) aidx = cnt - 1;
    const float* Arow = g_H + ((size_t)e * MAXP + aidx) * F_DIM + ak;

    int bn = (tid & 31) * 4;
    int bk = tid >> 5;
    const float* Bp = Bw + (size_t)bk * D_MODEL + bn;

    int tx = tid & 15, ty = tid >> 4;

    float acc[8][8];
#pragma unroll
    for (int i = 0; i < 8; i++)
#pragma unroll
        for (int j = 0; j < 8; j++) acc[i][j] = 0.f;

    for (int k0 = 0; k0 < F_DIM; k0 += BK) {
        float4 av = *(const float4*)(Arow + k0);
        As[ak + 0][am] = av.x; As[ak + 1][am] = av.y;
        As[ak + 2][am] = av.z; As[ak + 3][am] = av.w;
        *(float4*)&Bs[bk][bn] = *(const float4*)(Bp + (size_t)k0 * D_MODEL);
        __syncthreads();
#pragma unroll
        for (int kk = 0; kk < BK; kk++) {
            float a[8], b[8];
            *(float4*)(a)     = *(const float4*)&As[kk][ty * 8];
            *(float4*)(a + 4) = *(const float4*)&As[kk][ty * 8 + 4];
            *(float4*)(b)     = *(const float4*)&Bs[kk][tx * 8];
            *(float4*)(b + 4) = *(const float4*)&Bs[kk][tx * 8 + 4];
#pragma unroll
            for (int i = 0; i < 8; i++)
#pragma unroll
                for (int j = 0; j < 8; j++) acc[i][j] += a[i] * b[j];
        }
        __syncthreads();
    }

    float bb[8];
#pragma unroll
    for (int j = 0; j < 8; j++) bb[j] = b2[e * D_MODEL + n0 + tx * 8 + j];

#pragma unroll
    for (int i = 0; i < 8; i++) {
        int row = m0 + ty * 8 + i;
        if (row < cnt) {
            float wt = g_wt[e * MAXP + row];
            float* Or = g_O + ((size_t)e * MAXP + row) * D_MODEL + n0 + tx * 8;
            float4 o0, o1;
            o0.x = wt * (acc[i][0] + bb[0]);
            o0.y = wt * (acc[i][1] + bb[1]);
            o0.z = wt * (acc[i][2] + bb[2]);
            o0.w = wt * (acc[i][3] + bb[3]);
            o1.x = wt * (acc[i][4] + bb[4]);
            o1.y = wt * (acc[i][5] + bb[5]);
            o1.z = wt * (acc[i][6] + bb[6]);
            o1.w = wt * (acc[i][7] + bb[7]);
            *(float4*)(Or)     = o0;
            *(float4*)(Or + 4) = o1;
        }
    }
}

// ---------------------------------------------------------------------------
// Combine + residual + LayerNorm. One block (256 thr) per token; 4 floats/thr.
__global__ void ln_kernel(const float* __restrict__ x,
                          const float* __restrict__ gamma,
                          const float* __restrict__ beta,
                          float* __restrict__ out) {
    int t   = blockIdx.x;
    int tid = threadIdx.x;

    int s0 = g_slot[t * 2 + 0];
    int s1 = g_slot[t * 2 + 1];

    const float4* xr = (const float4*)(x + (size_t)t * D_MODEL);
    const float4* o0 = (const float4*)(g_O + (size_t)s0 * D_MODEL);
    const float4* o1 = (const float4*)(g_O + (size_t)s1 * D_MODEL);

    float4 xv = xr[tid];
    float4 a  = o0[tid];
    float4 b  = o1[tid];
    float4 y;
    y.x = xv.x + a.x + b.x;
    y.y = xv.y + a.y + b.y;
    y.z = xv.z + a.z + b.z;
    y.w = xv.w + a.w + b.w;

    float s  = y.x + y.y + y.z + y.w;
    float sq = y.x * y.x + y.y * y.y + y.z * y.z + y.w * y.w;

    __shared__ float red[18];
#pragma unroll
    for (int off = 16; off > 0; off >>= 1) {
        s  += __shfl_down_sync(0xffffffffu, s,  off);
        sq += __shfl_down_sync(0xffffffffu, sq, off);
    }
    int warp = tid >> 5, lane = tid & 31;
    __shared__ float ws[8], wq[8];
    if (lane == 0) { ws[warp] = s; wq[warp] = sq; }
    __syncthreads();
    if (tid == 0) {
        float ts = 0.f, tq = 0.f;
#pragma unroll
        for (int i = 0; i < 8; i++) { ts += ws[i]; tq += wq[i]; }
        red[16] = ts; red[17] = tq;
    }
    __syncthreads();

    float mu  = red[16] * (1.0f / D_MODEL);
    float var = red[17] * (1.0f / D_MODEL) - mu * mu;
    float inv = rsqrtf(var + LN_EPS);

    float4 g  = ((const float4*)gamma)[tid];
    float4 bt = ((const float4*)beta)[tid];
    float4 o;
    o.x = g.x * (y.x - mu) * inv + bt.x;
    o.y = g.y * (y.y - mu) * inv + bt.y;
    o.z = g.z * (y.z - mu) * inv + bt.z;
    o.w = g.w * (y.w - mu) * inv + bt.w;
    ((float4*)out)[(size_t)t * (D_MODEL / 4) + tid] = o;
}

// ---------------------------------------------------------------------------
extern "C" void kernel_launch(void* const* d_in, const int* in_sizes, int n_in,
                              void* d_out, int out_size) {
    const float* x     = (const float*)d_in[0];
    const float* Wg    = (const float*)d_in[1];
    const float* bg    = (const float*)d_in[2];
    const float* W1    = (const float*)d_in[3];
    const float* b1    = (const float*)d_in[4];
    const float* W2    = (const float*)d_in[5];
    const float* b2    = (const float*)d_in[6];
    const float* gamma = (const float*)d_in[7];
    const float* beta  = (const float*)d_in[8];
    float* out = (float*)d_out;

    init_kernel<<<1, 32>>>();
    gating_kernel<<<T_TOKENS / 8, 256>>>(x, Wg, bg);

    dim3 g1(F_DIM / BN, MAXP / BM, N_EXP);   // 16 x 32 x 8
    gemm1_kernel<<<g1, 256>>>(x, W1, b1);

    dim3 g2(D_MODEL / BN, MAXP / BM, N_EXP); // 8 x 32 x 8
    gemm2_kernel<<<g2, 256>>>(W2, b2);

    ln_kernel<<<T_TOKENS, 256>>>(x, gamma, beta, out);
}

// round 6
// speedup vs baseline: 1.8066x; 1.8066x over previous
#include <cuda_runtime.h>
#include <cuda_bf16.h>
#include <stdint.h>
#include <math.h>

#define T_TOKENS 4096
#define D_MODEL  1024
#define N_EXP    8
#define F_DIM    2048
#define LN_EPS   1e-5f
#define MAXP     4096

// tiles
#define BM 128
#define BN 128
#define BK 32
#define ROWB 80                         // 64B data + 16B pad: 20-word stride, conflict-free
#define BUFB (128 * ROWB)               // 10240 bytes per operand buffer
#define AHI 0
#define ALO (1 * BUFB)
#define BHI (2 * BUFB)
#define BLO (3 * BUFB)
#define TILES_BYTES (4 * BUFB)          // 40960 (static shared, < 48KB)

__device__ __forceinline__ void mma16816(float* c, const uint32_t* a, const uint32_t* b) {
    asm volatile(
        "mma.sync.aligned.m16n8k16.row.col.f32.bf16.bf16.f32 "
        "{%0,%1,%2,%3}, {%4,%5,%6,%7}, {%8,%9}, {%0,%1,%2,%3};"
        : "+f"(c[0]), "+f"(c[1]), "+f"(c[2]), "+f"(c[3])
        : "r"(a[0]), "r"(a[1]), "r"(a[2]), "r"(a[3]), "r"(b[0]), "r"(b[1]));
}

// ---------------- scratch ----------------
__device__ int   g_counts[N_EXP];
__device__ int   g_tok[N_EXP * MAXP];
__device__ float g_wt[N_EXP * MAXP];
__device__ int   g_slot[T_TOKENS * 2];
__device__ __align__(16) __nv_bfloat16 g_xhi[(size_t)T_TOKENS * D_MODEL];
__device__ __align__(16) __nv_bfloat16 g_xlo[(size_t)T_TOKENS * D_MODEL];
__device__ __align__(16) __nv_bfloat16 g_W1hi[(size_t)N_EXP * F_DIM * D_MODEL]; // [e][f][d]
__device__ __align__(16) __nv_bfloat16 g_W1lo[(size_t)N_EXP * F_DIM * D_MODEL];
__device__ __align__(16) __nv_bfloat16 g_W2hi[(size_t)N_EXP * D_MODEL * F_DIM]; // [e][d][f]
__device__ __align__(16) __nv_bfloat16 g_W2lo[(size_t)N_EXP * D_MODEL * F_DIM];
__device__ __align__(16) __nv_bfloat16 g_Hhi[(size_t)N_EXP * MAXP * F_DIM];
__device__ __align__(16) __nv_bfloat16 g_Hlo[(size_t)N_EXP * MAXP * F_DIM];
__device__ __align__(16) float g_O[(size_t)N_EXP * MAXP * D_MODEL];

// ---------------------------------------------------------------------------
__global__ void init_kernel() {
    if (threadIdx.x < N_EXP) g_counts[threadIdx.x] = 0;
}

// ---------------------------------------------------------------------------
__global__ void gating_kernel(const float* __restrict__ x,
                              const float* __restrict__ Wg,
                              const float* __restrict__ bg) {
    int warp = threadIdx.x >> 5;
    int lane = threadIdx.x & 31;
    int t = blockIdx.x * 8 + warp;
    if (t >= T_TOKENS) return;

    float acc[8];
#pragma unroll
    for (int e = 0; e < 8; e++) acc[e] = 0.f;
    const float* xr = x + (size_t)t * D_MODEL;
    for (int k = lane; k < D_MODEL; k += 32) {
        float xv = xr[k];
        float4 w0 = *(const float4*)(Wg + (size_t)k * 8);
        float4 w1 = *(const float4*)(Wg + (size_t)k * 8 + 4);
        acc[0] += xv * w0.x; acc[1] += xv * w0.y;
        acc[2] += xv * w0.z; acc[3] += xv * w0.w;
        acc[4] += xv * w1.x; acc[5] += xv * w1.y;
        acc[6] += xv * w1.z; acc[7] += xv * w1.w;
    }
#pragma unroll
    for (int e = 0; e < 8; e++)
#pragma unroll
        for (int off = 16; off > 0; off >>= 1)
            acc[e] += __shfl_down_sync(0xffffffffu, acc[e], off);

    if (lane == 0) {
        float v[8];
#pragma unroll
        for (int e = 0; e < 8; e++) v[e] = acc[e] + bg[e];
        int b0 = 0; float m0 = v[0];
#pragma unroll
        for (int e = 1; e < 8; e++) if (v[e] > m0) { m0 = v[e]; b0 = e; }
        int b1i = (b0 == 0) ? 1 : 0; float m1 = v[b1i];
#pragma unroll
        for (int e = 0; e < 8; e++)
            if (e != b0 && v[e] > m1) { m1 = v[e]; b1i = e; }

        float ex = expf(m1 - m0);
        float s  = 1.0f + ex;
        int p0 = atomicAdd(&g_counts[b0], 1);
        g_tok[b0 * MAXP + p0] = t;
        g_wt [b0 * MAXP + p0] = 1.0f / s;
        g_slot[t * 2 + 0] = b0 * MAXP + p0;
        int p1 = atomicAdd(&g_counts[b1i], 1);
        g_tok[b1i * MAXP + p1] = t;
        g_wt [b1i * MAXP + p1] = ex / s;
        g_slot[t * 2 + 1] = b1i * MAXP + p1;
    }
}

// ---------------------------------------------------------------------------
// fp32 -> bf16 hi/lo split of x (globals referenced in DEVICE code)
__global__ void convert_x_kernel(const float* __restrict__ x) {
    int i = blockIdx.x * blockDim.x + threadIdx.x;   // group of 4 elements
    float4 v = ((const float4*)x)[i];
    __nv_bfloat16 h0 = __float2bfloat16(v.x), h1 = __float2bfloat16(v.y);
    __nv_bfloat16 h2 = __float2bfloat16(v.z), h3 = __float2bfloat16(v.w);
    __nv_bfloat162 a, b;
    a.x = h0; a.y = h1; b.x = h2; b.y = h3;
    ((__nv_bfloat162*)g_xhi)[i * 2 + 0] = a;
    ((__nv_bfloat162*)g_xhi)[i * 2 + 1] = b;
    a.x = __float2bfloat16(v.x - __bfloat162float(h0));
    a.y = __float2bfloat16(v.y - __bfloat162float(h1));
    b.x = __float2bfloat16(v.z - __bfloat162float(h2));
    b.y = __float2bfloat16(v.w - __bfloat162float(h3));
    ((__nv_bfloat162*)g_xlo)[i * 2 + 0] = a;
    ((__nv_bfloat162*)g_xlo)[i * 2 + 1] = b;
}

// ---------------------------------------------------------------------------
// W [E][R][C] fp32 -> hi/lo bf16 [E][C][R].
// NOTE: hi/lo pointers MUST be resolved in device code (device-global symbol
// addresses taken on the host are host shadow addresses; on GB300 ATS those
// writes silently land in host memory — the R3-R5 zero-weights bug).
__device__ __forceinline__ void transpose_body(const float* __restrict__ W,
                                               __nv_bfloat16* __restrict__ hi,
                                               __nv_bfloat16* __restrict__ lo,
                                               int R, int C) {
    __shared__ float t[32][33];
    int e  = blockIdx.z;
    int c0 = blockIdx.x * 32, r0 = blockIdx.y * 32;
    int tx = threadIdx.x, ty = threadIdx.y;
    const float* Wp = W + (size_t)e * R * C;
#pragma unroll
    for (int i = 0; i < 32; i += 8)
        t[ty + i][tx] = Wp[(size_t)(r0 + ty + i) * C + (c0 + tx)];
    __syncthreads();
    size_t ob = (size_t)e * C * R;
#pragma unroll
    for (int i = 0; i < 32; i += 8) {
        float v = t[tx][ty + i];
        __nv_bfloat16 h = __float2bfloat16(v);
        size_t o = ob + (size_t)(c0 + ty + i) * R + (r0 + tx);
        hi[o] = h;
        lo[o] = __float2bfloat16(v - __bfloat162float(h));
    }
}
__global__ void transpose_w1_kernel(const float* __restrict__ W) {
    transpose_body(W, g_W1hi, g_W1lo, D_MODEL, F_DIM);   // device-resolved symbols
}
__global__ void transpose_w2_kernel(const float* __restrict__ W) {
    transpose_body(W, g_W2hi, g_W2lo, F_DIM, D_MODEL);
}

// ---------------------------------------------------------------------------
// Shared HMMA pieces.
// smem writer contract: element (row, k_local) of each operand buffer lives at
//   buffer_base + row*ROWB + 2*k_local    (rows 0..127, k_local 0..31)
struct RowPtrs {
    const uint4* ah;  // per-thread A row (hi), at k=0
    const uint4* al;
    const uint4* bh;
    const uint4* bl;
};
struct Stage {
    uint4 ah[2], al[2], bh[2], bl[2];
};

__device__ __forceinline__ void ldg_stage(Stage& st, const RowPtrs& rp, int kt, int half) {
    int idx = kt * 4 + half * 2;
    st.ah[0] = rp.ah[idx]; st.ah[1] = rp.ah[idx + 1];
    st.al[0] = rp.al[idx]; st.al[1] = rp.al[idx + 1];
    st.bh[0] = rp.bh[idx]; st.bh[1] = rp.bh[idx + 1];
    st.bl[0] = rp.bl[idx]; st.bl[1] = rp.bl[idx + 1];
}
__device__ __forceinline__ void sts_stage(char* tiles, const Stage& st, int row, int half) {
    uint32_t off = (uint32_t)row * ROWB + (uint32_t)half * 32u;
    *(uint4*)(tiles + AHI + off)      = st.ah[0];
    *(uint4*)(tiles + AHI + off + 16) = st.ah[1];
    *(uint4*)(tiles + ALO + off)      = st.al[0];
    *(uint4*)(tiles + ALO + off + 16) = st.al[1];
    *(uint4*)(tiles + BHI + off)      = st.bh[0];
    *(uint4*)(tiles + BHI + off + 16) = st.bh[1];
    *(uint4*)(tiles + BLO + off)      = st.bl[0];
    *(uint4*)(tiles + BLO + off + 16) = st.bl[1];
}

// Per the PTX ISA m16n8k16 fragment tables:
//   A: a0=(row,k) a1=(row+8,k) a2=(row,k+8) a3=(row+8,k+8),
//      row = wtile_m + (lane>>2), k = khalf*16 + (lane&3)*2
//   B: b0=(k..k+1, n) b1=(k+8..k+9, n),  n = wtile_n + (lane>>2)
__device__ __forceinline__ void compute_tiles(const char* tiles, int wr, int wc,
                                              int lane, float c[4][4][4]) {
    uint32_t arow0 = (uint32_t)(wr * 64 + (lane >> 2)) * ROWB;
    uint32_t brow0 = (uint32_t)(wc * 32 + (lane >> 2)) * ROWB;
    uint32_t kb    = (uint32_t)(lane & 3) * 4u;
#pragma unroll
    for (int kk = 0; kk < 2; kk++) {
        uint32_t ko = (uint32_t)kk * 32u + kb;
        uint32_t ah[4][4], al[4][4], bh[4][2], bl[4][2];
#pragma unroll
        for (int mt = 0; mt < 4; mt++) {
            const char* r0 = tiles + AHI + arow0 + (uint32_t)(mt * 16) * ROWB + ko;
            ah[mt][0] = *(const uint32_t*)(r0);
            ah[mt][1] = *(const uint32_t*)(r0 + 8 * ROWB);
            ah[mt][2] = *(const uint32_t*)(r0 + 16);
            ah[mt][3] = *(const uint32_t*)(r0 + 8 * ROWB + 16);
        }
#pragma unroll
        for (int nt = 0; nt < 4; nt++) {
            const char* r0 = tiles + BHI + brow0 + (uint32_t)(nt * 8) * ROWB + ko;
            bh[nt][0] = *(const uint32_t*)(r0);
            bh[nt][1] = *(const uint32_t*)(r0 + 16);
        }
#pragma unroll
        for (int mt = 0; mt < 4; mt++)
#pragma unroll
            for (int nt = 0; nt < 4; nt++)
                mma16816(c[mt][nt], ah[mt], bh[nt]);
#pragma unroll
        for (int mt = 0; mt < 4; mt++) {
            const char* r0 = tiles + ALO + arow0 + (uint32_t)(mt * 16) * ROWB + ko;
            al[mt][0] = *(const uint32_t*)(r0);
            al[mt][1] = *(const uint32_t*)(r0 + 8 * ROWB);
            al[mt][2] = *(const uint32_t*)(r0 + 16);
            al[mt][3] = *(const uint32_t*)(r0 + 8 * ROWB + 16);
        }
#pragma unroll
        for (int mt = 0; mt < 4; mt++)
#pragma unroll
            for (int nt = 0; nt < 4; nt++)
                mma16816(c[mt][nt], al[mt], bh[nt]);
#pragma unroll
        for (int nt = 0; nt < 4; nt++) {
            const char* r0 = tiles + BLO + brow0 + (uint32_t)(nt * 8) * ROWB + ko;
            bl[nt][0] = *(const uint32_t*)(r0);
            bl[nt][1] = *(const uint32_t*)(r0 + 16);
        }
#pragma unroll
        for (int mt = 0; mt < 4; mt++)
#pragma unroll
            for (int nt = 0; nt < 4; nt++)
                mma16816(c[mt][nt], ah[mt], bl[nt]);
    }
}

__device__ __forceinline__ void run_mainloop(char* tiles, const RowPtrs& rp,
                                             int ktiles, int wr, int wc, int lane,
                                             float c[4][4][4], int row, int half) {
    Stage st;
    ldg_stage(st, rp, 0, half);
    for (int kt = 0; kt < ktiles; kt++) {
        sts_stage(tiles, st, row, half);
        __syncthreads();
        if (kt + 1 < ktiles) ldg_stage(st, rp, kt + 1, half);
        compute_tiles(tiles, wr, wc, lane, c);
        __syncthreads();
    }
}

// ---------------------------------------------------------------------------
// GEMM1: H[e-rows, F] = relu( Xg @ W1t[e] + b1[e] ), 3-pass bf16 hi/lo
__global__ void __launch_bounds__(256, 1)
gemm1_mma(const float* __restrict__ b1) {
    __shared__ __align__(16) char tiles[TILES_BYTES];
    int e   = blockIdx.z;
    int cnt = g_counts[e];
    int m0  = blockIdx.y * BM;
    if (m0 >= cnt) return;
    int n0  = blockIdx.x * BN;
    int tid = threadIdx.x, lane = tid & 31, wid = tid >> 5;
    int wr = wid >> 2, wc = wid & 3;
    int row = tid >> 1, half = tid & 1;

    int arow = m0 + row; if (arow >= cnt) arow = cnt - 1;
    int tok  = g_tok[e * MAXP + arow];
    int brow = n0 + row;
    RowPtrs rp;
    rp.ah = (const uint4*)(g_xhi + (size_t)tok * D_MODEL);
    rp.al = (const uint4*)(g_xlo + (size_t)tok * D_MODEL);
    rp.bh = (const uint4*)(g_W1hi + ((size_t)e * F_DIM + brow) * D_MODEL);
    rp.bl = (const uint4*)(g_W1lo + ((size_t)e * F_DIM + brow) * D_MODEL);

    float c[4][4][4];
#pragma unroll
    for (int i = 0; i < 4; i++)
#pragma unroll
        for (int j = 0; j < 4; j++)
#pragma unroll
            for (int k = 0; k < 4; k++) c[i][j][k] = 0.f;

    run_mainloop(tiles, rp, D_MODEL / BK, wr, wc, lane, c, row, half);

    // epilogue: bias + relu + hi/lo split -> g_Hhi/g_Hlo (register-direct)
    int lrow = lane >> 2, lcol2 = (lane & 3) * 2;
#pragma unroll
    for (int nt = 0; nt < 4; nt++) {
        int col = n0 + wc * 32 + nt * 8 + lcol2;
        float bb0 = b1[e * F_DIM + col];
        float bb1 = b1[e * F_DIM + col + 1];
#pragma unroll
        for (int mt = 0; mt < 4; mt++) {
            int r0 = m0 + wr * 64 + mt * 16 + lrow;
#pragma unroll
            for (int h = 0; h < 2; h++) {
                int r = r0 + h * 8;
                if (r < cnt) {
                    float v0 = fmaxf(c[mt][nt][h * 2 + 0] + bb0, 0.f);
                    float v1 = fmaxf(c[mt][nt][h * 2 + 1] + bb1, 0.f);
                    __nv_bfloat16 h0 = __float2bfloat16(v0);
                    __nv_bfloat16 h1 = __float2bfloat16(v1);
                    __nv_bfloat162 hi, lo;
                    hi.x = h0; hi.y = h1;
                    lo.x = __float2bfloat16(v0 - __bfloat162float(h0));
                    lo.y = __float2bfloat16(v1 - __bfloat162float(h1));
                    size_t o = ((size_t)e * MAXP + r) * F_DIM + col;
                    *(__nv_bfloat162*)(g_Hhi + o) = hi;
                    *(__nv_bfloat162*)(g_Hlo + o) = lo;
                }
            }
        }
    }
}

// ---------------------------------------------------------------------------
// GEMM2: O[e-rows, D] = wt * ( H @ W2t[e] + b2[e] )
__global__ void __launch_bounds__(256, 1)
gemm2_mma(const float* __restrict__ b2) {
    __shared__ __align__(16) char tiles[TILES_BYTES];
    int e   = blockIdx.z;
    int cnt = g_counts[e];
    int m0  = blockIdx.y * BM;
    if (m0 >= cnt) return;
    int n0  = blockIdx.x * BN;
    int tid = threadIdx.x, lane = tid & 31, wid = tid >> 5;
    int wr = wid >> 2, wc = wid & 3;
    int row = tid >> 1, half = tid & 1;

    int arow = m0 + row; if (arow >= cnt) arow = cnt - 1;
    int brow = n0 + row;
    RowPtrs rp;
    rp.ah = (const uint4*)(g_Hhi + ((size_t)e * MAXP + arow) * F_DIM);
    rp.al = (const uint4*)(g_Hlo + ((size_t)e * MAXP + arow) * F_DIM);
    rp.bh = (const uint4*)(g_W2hi + ((size_t)e * D_MODEL + brow) * F_DIM);
    rp.bl = (const uint4*)(g_W2lo + ((size_t)e * D_MODEL + brow) * F_DIM);

    float c[4][4][4];
#pragma unroll
    for (int i = 0; i < 4; i++)
#pragma unroll
        for (int j = 0; j < 4; j++)
#pragma unroll
            for (int k = 0; k < 4; k++) c[i][j][k] = 0.f;

    run_mainloop(tiles, rp, F_DIM / BK, wr, wc, lane, c, row, half);

    // epilogue: (acc + bias) * wt -> g_O (fp32)
    int lrow = lane >> 2, lcol2 = (lane & 3) * 2;
#pragma unroll
    for (int nt = 0; nt < 4; nt++) {
        int col = n0 + wc * 32 + nt * 8 + lcol2;
        float bb0 = b2[e * D_MODEL + col];
        float bb1 = b2[e * D_MODEL + col + 1];
#pragma unroll
        for (int mt = 0; mt < 4; mt++) {
            int r0 = m0 + wr * 64 + mt * 16 + lrow;
#pragma unroll
            for (int h = 0; h < 2; h++) {
                int r = r0 + h * 8;
                if (r < cnt) {
                    float wt = g_wt[e * MAXP + r];
                    float2 o;
                    o.x = (c[mt][nt][h * 2 + 0] + bb0) * wt;
                    o.y = (c[mt][nt][h * 2 + 1] + bb1) * wt;
                    *(float2*)(g_O + ((size_t)e * MAXP + r) * D_MODEL + col) = o;
                }
            }
        }
    }
}

// ---------------------------------------------------------------------------
__global__ void ln_kernel(const float* __restrict__ x,
                          const float* __restrict__ gamma,
                          const float* __restrict__ beta,
                          float* __restrict__ out) {
    int t   = blockIdx.x;
    int tid = threadIdx.x;
    int s0 = g_slot[t * 2 + 0];
    int s1 = g_slot[t * 2 + 1];

    const float4* xr = (const float4*)(x + (size_t)t * D_MODEL);
    const float4* o0 = (const float4*)(g_O + (size_t)s0 * D_MODEL);
    const float4* o1 = (const float4*)(g_O + (size_t)s1 * D_MODEL);

    float4 xv = xr[tid];
    float4 a  = o0[tid];
    float4 b  = o1[tid];
    float4 y;
    y.x = xv.x + a.x + b.x;
    y.y = xv.y + a.y + b.y;
    y.z = xv.z + a.z + b.z;
    y.w = xv.w + a.w + b.w;

    float s  = y.x + y.y + y.z + y.w;
    float sq = y.x * y.x + y.y * y.y + y.z * y.z + y.w * y.w;
#pragma unroll
    for (int off = 16; off > 0; off >>= 1) {
        s  += __shfl_down_sync(0xffffffffu, s,  off);
        sq += __shfl_down_sync(0xffffffffu, sq, off);
    }
    int warp = tid >> 5, lane = tid & 31;
    __shared__ float ws[8], wq[8], red[2];
    if (lane == 0) { ws[warp] = s; wq[warp] = sq; }
    __syncthreads();
    if (tid == 0) {
        float ts = 0.f, tq = 0.f;
#pragma unroll
        for (int i = 0; i < 8; i++) { ts += ws[i]; tq += wq[i]; }
        red[0] = ts; red[1] = tq;
    }
    __syncthreads();

    float mu  = red[0] * (1.0f / D_MODEL);
    float var = red[1] * (1.0f / D_MODEL) - mu * mu;
    float inv = rsqrtf(var + LN_EPS);

    float4 g  = ((const float4*)gamma)[tid];
    float4 bt = ((const float4*)beta)[tid];
    float4 o;
    o.x = g.x * (y.x - mu) * inv + bt.x;
    o.y = g.y * (y.y - mu) * inv + bt.y;
    o.z = g.z * (y.z - mu) * inv + bt.z;
    o.w = g.w * (y.w - mu) * inv + bt.w;
    ((float4*)out)[(size_t)t * (D_MODEL / 4) + tid] = o;
}

// ---------------------------------------------------------------------------
extern "C" void kernel_launch(void* const* d_in, const int* in_sizes, int n_in,
                              void* d_out, int out_size) {
    const float* x     = (const float*)d_in[0];
    const float* Wg    = (const float*)d_in[1];
    const float* bg    = (const float*)d_in[2];
    const float* W1    = (const float*)d_in[3];
    const float* b1    = (const float*)d_in[4];
    const float* W2    = (const float*)d_in[5];
    const float* b2    = (const float*)d_in[6];
    const float* gamma = (const float*)d_in[7];
    const float* beta  = (const float*)d_in[8];
    float* out = (float*)d_out;

    init_kernel<<<1, 32>>>();
    gating_kernel<<<T_TOKENS / 8, 256>>>(x, Wg, bg);
    convert_x_kernel<<<T_TOKENS * D_MODEL / 4 / 256, 256>>>(x);
    transpose_w1_kernel<<<dim3(F_DIM / 32, D_MODEL / 32, N_EXP), dim3(32, 8)>>>(W1);
    transpose_w2_kernel<<<dim3(D_MODEL / 32, F_DIM / 32, N_EXP), dim3(32, 8)>>>(W2);

    gemm1_mma<<<dim3(F_DIM / BN, MAXP / BM, N_EXP), 256>>>(b1);
    gemm2_mma<<<dim3(D_MODEL / BN, MAXP / BM, N_EXP), 256>>>(b2);

    ln_kernel<<<T_TOKENS, 256>>>(x, gamma, beta, out);
}

// round 7
// speedup vs baseline: 1.8959x; 1.0495x over previous
#include <cuda_runtime.h>
#include <cuda_bf16.h>
#include <stdint.h>
#include <math.h>

#define T_TOKENS 4096
#define D_MODEL  1024
#define N_EXP    8
#define F_DIM    2048
#define LN_EPS   1e-5f
#define MAXP     4096

// tiles
#define BM 128
#define BN 128
#define BK 32
#define STAGES 3
#define ROWB 80                         // 64B data + 16B pad: 20-word stride, conflict-free
#define BUFB (128 * ROWB)               // 10240 bytes per operand buffer
#define AHI 0
#define ALO (1 * BUFB)
#define BHI (2 * BUFB)
#define BLO (3 * BUFB)
#define STG_BYTES (4 * BUFB)            // 40960 per stage
#define SMEM_BYTES (STAGES * STG_BYTES) // 122880 dynamic

__device__ __forceinline__ void mma16816(float* c, const uint32_t* a, const uint32_t* b) {
    asm volatile(
        "mma.sync.aligned.m16n8k16.row.col.f32.bf16.bf16.f32 "
        "{%0,%1,%2,%3}, {%4,%5,%6,%7}, {%8,%9}, {%0,%1,%2,%3};"
        : "+f"(c[0]), "+f"(c[1]), "+f"(c[2]), "+f"(c[3])
        : "r"(a[0]), "r"(a[1]), "r"(a[2]), "r"(a[3]), "r"(b[0]), "r"(b[1]));
}
__device__ __forceinline__ uint32_t smem_u32(const void* p) {
    uint32_t a;
    asm("{ .reg .u64 t; cvta.to.shared.u64 t, %1; cvt.u32.u64 %0, t; }"
        : "=r"(a) : "l"(p));
    return a;
}
__device__ __forceinline__ void cp16(uint32_t saddr, const void* g) {
    asm volatile("cp.async.cg.shared.global [%0], [%1], 16;"
                 :: "r"(saddr), "l"(g) : "memory");
}
#define CP_COMMIT() asm volatile("cp.async.commit_group;" ::: "memory")
#define CP_WAIT1()  asm volatile("cp.async.wait_group 1;" ::: "memory")

// ---------------- scratch ----------------
__device__ int   g_counts[N_EXP];
__device__ int   g_tok[N_EXP * MAXP];
__device__ float g_wt[N_EXP * MAXP];
__device__ int   g_slot[T_TOKENS * 2];
__device__ __align__(16) __nv_bfloat16 g_xhi[(size_t)T_TOKENS * D_MODEL];
__device__ __align__(16) __nv_bfloat16 g_xlo[(size_t)T_TOKENS * D_MODEL];
__device__ __align__(16) __nv_bfloat16 g_W1hi[(size_t)N_EXP * F_DIM * D_MODEL]; // [e][f][d]
__device__ __align__(16) __nv_bfloat16 g_W1lo[(size_t)N_EXP * F_DIM * D_MODEL];
__device__ __align__(16) __nv_bfloat16 g_W2hi[(size_t)N_EXP * D_MODEL * F_DIM]; // [e][d][f]
__device__ __align__(16) __nv_bfloat16 g_W2lo[(size_t)N_EXP * D_MODEL * F_DIM];
__device__ __align__(16) __nv_bfloat16 g_Hhi[(size_t)N_EXP * MAXP * F_DIM];
__device__ __align__(16) __nv_bfloat16 g_Hlo[(size_t)N_EXP * MAXP * F_DIM];
__device__ __align__(16) float g_O[(size_t)N_EXP * MAXP * D_MODEL];

// ---------------------------------------------------------------------------
__global__ void init_kernel() {
    if (threadIdx.x < N_EXP) g_counts[threadIdx.x] = 0;
}

// ---------------------------------------------------------------------------
__global__ void gating_kernel(const float* __restrict__ x,
                              const float* __restrict__ Wg,
                              const float* __restrict__ bg) {
    int warp = threadIdx.x >> 5;
    int lane = threadIdx.x & 31;
    int t = blockIdx.x * 8 + warp;
    if (t >= T_TOKENS) return;

    float acc[8];
#pragma unroll
    for (int e = 0; e < 8; e++) acc[e] = 0.f;
    const float* xr = x + (size_t)t * D_MODEL;
    for (int k = lane; k < D_MODEL; k += 32) {
        float xv = xr[k];
        float4 w0 = *(const float4*)(Wg + (size_t)k * 8);
        float4 w1 = *(const float4*)(Wg + (size_t)k * 8 + 4);
        acc[0] += xv * w0.x; acc[1] += xv * w0.y;
        acc[2] += xv * w0.z; acc[3] += xv * w0.w;
        acc[4] += xv * w1.x; acc[5] += xv * w1.y;
        acc[6] += xv * w1.z; acc[7] += xv * w1.w;
    }
#pragma unroll
    for (int e = 0; e < 8; e++)
#pragma unroll
        for (int off = 16; off > 0; off >>= 1)
            acc[e] += __shfl_down_sync(0xffffffffu, acc[e], off);

    if (lane == 0) {
        float v[8];
#pragma unroll
        for (int e = 0; e < 8; e++) v[e] = acc[e] + bg[e];
        int b0 = 0; float m0 = v[0];
#pragma unroll
        for (int e = 1; e < 8; e++) if (v[e] > m0) { m0 = v[e]; b0 = e; }
        int b1i = (b0 == 0) ? 1 : 0; float m1 = v[b1i];
#pragma unroll
        for (int e = 0; e < 8; e++)
            if (e != b0 && v[e] > m1) { m1 = v[e]; b1i = e; }

        float ex = expf(m1 - m0);
        float s  = 1.0f + ex;
        int p0 = atomicAdd(&g_counts[b0], 1);
        g_tok[b0 * MAXP + p0] = t;
        g_wt [b0 * MAXP + p0] = 1.0f / s;
        g_slot[t * 2 + 0] = b0 * MAXP + p0;
        int p1 = atomicAdd(&g_counts[b1i], 1);
        g_tok[b1i * MAXP + p1] = t;
        g_wt [b1i * MAXP + p1] = ex / s;
        g_slot[t * 2 + 1] = b1i * MAXP + p1;
    }
}

// ---------------------------------------------------------------------------
// fp32 -> bf16 hi/lo split of x (globals referenced in DEVICE code)
__global__ void convert_x_kernel(const float* __restrict__ x) {
    int i = blockIdx.x * blockDim.x + threadIdx.x;   // group of 4 elements
    float4 v = ((const float4*)x)[i];
    __nv_bfloat16 h0 = __float2bfloat16(v.x), h1 = __float2bfloat16(v.y);
    __nv_bfloat16 h2 = __float2bfloat16(v.z), h3 = __float2bfloat16(v.w);
    __nv_bfloat162 a, b;
    a.x = h0; a.y = h1; b.x = h2; b.y = h3;
    ((__nv_bfloat162*)g_xhi)[i * 2 + 0] = a;
    ((__nv_bfloat162*)g_xhi)[i * 2 + 1] = b;
    a.x = __float2bfloat16(v.x - __bfloat162float(h0));
    a.y = __float2bfloat16(v.y - __bfloat162float(h1));
    b.x = __float2bfloat16(v.z - __bfloat162float(h2));
    b.y = __float2bfloat16(v.w - __bfloat162float(h3));
    ((__nv_bfloat162*)g_xlo)[i * 2 + 0] = a;
    ((__nv_bfloat162*)g_xlo)[i * 2 + 1] = b;
}

// ---------------------------------------------------------------------------
// W [E][R][C] fp32 -> hi/lo bf16 [E][C][R].
// hi/lo pointers MUST be device-resolved symbols (GB300 ATS: host-shadow
// addresses silently write host memory — the R3-R5 zero-weights bug).
__device__ __forceinline__ void transpose_body(const float* __restrict__ W,
                                               __nv_bfloat16* __restrict__ hi,
                                               __nv_bfloat16* __restrict__ lo,
                                               int R, int C) {
    __shared__ float t[32][33];
    int e  = blockIdx.z;
    int c0 = blockIdx.x * 32, r0 = blockIdx.y * 32;
    int tx = threadIdx.x, ty = threadIdx.y;
    const float* Wp = W + (size_t)e * R * C;
#pragma unroll
    for (int i = 0; i < 32; i += 8)
        t[ty + i][tx] = Wp[(size_t)(r0 + ty + i) * C + (c0 + tx)];
    __syncthreads();
    size_t ob = (size_t)e * C * R;
#pragma unroll
    for (int i = 0; i < 32; i += 8) {
        float v = t[tx][ty + i];
        __nv_bfloat16 h = __float2bfloat16(v);
        size_t o = ob + (size_t)(c0 + ty + i) * R + (r0 + tx);
        hi[o] = h;
        lo[o] = __float2bfloat16(v - __bfloat162float(h));
    }
}
__global__ void transpose_w1_kernel(const float* __restrict__ W) {
    transpose_body(W, g_W1hi, g_W1lo, D_MODEL, F_DIM);
}
__global__ void transpose_w2_kernel(const float* __restrict__ W) {
    transpose_body(W, g_W2hi, g_W2lo, F_DIM, D_MODEL);
}

// ---------------------------------------------------------------------------
// HMMA mainloop, cp.async 3-stage pipelined.
// smem writer contract: element (row, k_local) of each operand buffer lives at
//   stage_base + buf_off + row*ROWB + 2*k_local
struct RowPtrs {
    const uint4* ah;
    const uint4* al;
    const uint4* bh;
    const uint4* bl;
};

__device__ __forceinline__ void cp_stage(uint32_t smbase, const RowPtrs& rp,
                                         int s, int kt, int row, int half) {
    uint32_t off = (uint32_t)row * ROWB + (uint32_t)half * 32u;
    uint32_t b   = smbase + s * STG_BYTES + off;
    int idx = kt * 4 + half * 2;
    cp16(b + AHI,      rp.ah + idx);
    cp16(b + AHI + 16, rp.ah + idx + 1);
    cp16(b + ALO,      rp.al + idx);
    cp16(b + ALO + 16, rp.al + idx + 1);
    cp16(b + BHI,      rp.bh + idx);
    cp16(b + BHI + 16, rp.bh + idx + 1);
    cp16(b + BLO,      rp.bl + idx);
    cp16(b + BLO + 16, rp.bl + idx + 1);
}

// Per the PTX ISA m16n8k16 fragment tables (verified in R6):
//   A: a0=(row,k) a1=(row+8,k) a2=(row,k+8) a3=(row+8,k+8),
//      row = wtile_m + (lane>>2), k = khalf*16 + (lane&3)*2
//   B: b0=(k..k+1, n) b1=(k+8..k+9, n),  n = wtile_n + (lane>>2)
__device__ __forceinline__ void compute_tiles(const char* tiles, int wr, int wc,
                                              int lane, float c[4][4][4]) {
    uint32_t arow0 = (uint32_t)(wr * 64 + (lane >> 2)) * ROWB;
    uint32_t brow0 = (uint32_t)(wc * 32 + (lane >> 2)) * ROWB;
    uint32_t kb    = (uint32_t)(lane & 3) * 4u;
#pragma unroll
    for (int kk = 0; kk < 2; kk++) {
        uint32_t ko = (uint32_t)kk * 32u + kb;
        uint32_t ah[4][4], al[4][4], bh[4][2], bl[4][2];
#pragma unroll
        for (int mt = 0; mt < 4; mt++) {
            const char* r0 = tiles + AHI + arow0 + (uint32_t)(mt * 16) * ROWB + ko;
            ah[mt][0] = *(const uint32_t*)(r0);
            ah[mt][1] = *(const uint32_t*)(r0 + 8 * ROWB);
            ah[mt][2] = *(const uint32_t*)(r0 + 16);
            ah[mt][3] = *(const uint32_t*)(r0 + 8 * ROWB + 16);
        }
#pragma unroll
        for (int nt = 0; nt < 4; nt++) {
            const char* r0 = tiles + BHI + brow0 + (uint32_t)(nt * 8) * ROWB + ko;
            bh[nt][0] = *(const uint32_t*)(r0);
            bh[nt][1] = *(const uint32_t*)(r0 + 16);
        }
#pragma unroll
        for (int mt = 0; mt < 4; mt++)
#pragma unroll
            for (int nt = 0; nt < 4; nt++)
                mma16816(c[mt][nt], ah[mt], bh[nt]);
#pragma unroll
        for (int mt = 0; mt < 4; mt++) {
            const char* r0 = tiles + ALO + arow0 + (uint32_t)(mt * 16) * ROWB + ko;
            al[mt][0] = *(const uint32_t*)(r0);
            al[mt][1] = *(const uint32_t*)(r0 + 8 * ROWB);
            al[mt][2] = *(const uint32_t*)(r0 + 16);
            al[mt][3] = *(const uint32_t*)(r0 + 8 * ROWB + 16);
        }
#pragma unroll
        for (int mt = 0; mt < 4; mt++)
#pragma unroll
            for (int nt = 0; nt < 4; nt++)
                mma16816(c[mt][nt], al[mt], bh[nt]);
#pragma unroll
        for (int nt = 0; nt < 4; nt++) {
            const char* r0 = tiles + BLO + brow0 + (uint32_t)(nt * 8) * ROWB + ko;
            bl[nt][0] = *(const uint32_t*)(r0);
            bl[nt][1] = *(const uint32_t*)(r0 + 16);
        }
#pragma unroll
        for (int mt = 0; mt < 4; mt++)
#pragma unroll
            for (int nt = 0; nt < 4; nt++)
                mma16816(c[mt][nt], ah[mt], bl[nt]);
    }
}

// One barrier per k-tile: all threads finish compute(kt-1) before anyone
// passes sync(kt); only afterwards are writes to stage (kt-1)%3 issued.
__device__ __forceinline__ void run_mainloop(char* tiles, uint32_t smbase,
                                             const RowPtrs& rp, int ktiles,
                                             int wr, int wc, int lane,
                                             float c[4][4][4], int row, int half) {
#pragma unroll
    for (int s = 0; s < STAGES - 1; s++) {
        cp_stage(smbase, rp, s, s, row, half);
        CP_COMMIT();
    }
    for (int kt = 0; kt < ktiles; kt++) {
        CP_WAIT1();
        __syncthreads();
        int kn = kt + STAGES - 1;
        if (kn < ktiles) cp_stage(smbase, rp, kn % STAGES, kn, row, half);
        CP_COMMIT();
        compute_tiles(tiles + (kt % STAGES) * STG_BYTES, wr, wc, lane, c);
    }
}

// ---------------------------------------------------------------------------
// GEMM1: H[e-rows, F] = relu( Xg @ W1t[e] + b1[e] ), 3-pass bf16 hi/lo
__global__ void __launch_bounds__(256, 1)
gemm1_mma(const float* __restrict__ b1) {
    extern __shared__ __align__(16) char tiles[];
    uint32_t smbase = smem_u32(tiles);
    int e   = blockIdx.z;
    int cnt = g_counts[e];
    int m0  = blockIdx.y * BM;
    if (m0 >= cnt) return;
    int n0  = blockIdx.x * BN;
    int tid = threadIdx.x, lane = tid & 31, wid = tid >> 5;
    int wr = wid >> 2, wc = wid & 3;
    int row = tid >> 1, half = tid & 1;

    int arow = m0 + row; if (arow >= cnt) arow = cnt - 1;
    int tok  = g_tok[e * MAXP + arow];
    int brow = n0 + row;
    RowPtrs rp;
    rp.ah = (const uint4*)(g_xhi + (size_t)tok * D_MODEL);
    rp.al = (const uint4*)(g_xlo + (size_t)tok * D_MODEL);
    rp.bh = (const uint4*)(g_W1hi + ((size_t)e * F_DIM + brow) * D_MODEL);
    rp.bl = (const uint4*)(g_W1lo + ((size_t)e * F_DIM + brow) * D_MODEL);

    float c[4][4][4];
#pragma unroll
    for (int i = 0; i < 4; i++)
#pragma unroll
        for (int j = 0; j < 4; j++)
#pragma unroll
            for (int k = 0; k < 4; k++) c[i][j][k] = 0.f;

    run_mainloop(tiles, smbase, rp, D_MODEL / BK, wr, wc, lane, c, row, half);

    // epilogue: bias + relu + hi/lo split -> g_Hhi/g_Hlo (register-direct)
    int lrow = lane >> 2, lcol2 = (lane & 3) * 2;
#pragma unroll
    for (int nt = 0; nt < 4; nt++) {
        int col = n0 + wc * 32 + nt * 8 + lcol2;
        float bb0 = b1[e * F_DIM + col];
        float bb1 = b1[e * F_DIM + col + 1];
#pragma unroll
        for (int mt = 0; mt < 4; mt++) {
            int r0 = m0 + wr * 64 + mt * 16 + lrow;
#pragma unroll
            for (int h = 0; h < 2; h++) {
                int r = r0 + h * 8;
                if (r < cnt) {
                    float v0 = fmaxf(c[mt][nt][h * 2 + 0] + bb0, 0.f);
                    float v1 = fmaxf(c[mt][nt][h * 2 + 1] + bb1, 0.f);
                    __nv_bfloat16 h0 = __float2bfloat16(v0);
                    __nv_bfloat16 h1 = __float2bfloat16(v1);
                    __nv_bfloat162 hi, lo;
                    hi.x = h0; hi.y = h1;
                    lo.x = __float2bfloat16(v0 - __bfloat162float(h0));
                    lo.y = __float2bfloat16(v1 - __bfloat162float(h1));
                    size_t o = ((size_t)e * MAXP + r) * F_DIM + col;
                    *(__nv_bfloat162*)(g_Hhi + o) = hi;
                    *(__nv_bfloat162*)(g_Hlo + o) = lo;
                }
            }
        }
    }
}

// ---------------------------------------------------------------------------
// GEMM2: O[e-rows, D] = wt * ( H @ W2t[e] + b2[e] )
__global__ void __launch_bounds__(256, 1)
gemm2_mma(const float* __restrict__ b2) {
    extern __shared__ __align__(16) char tiles[];
    uint32_t smbase = smem_u32(tiles);
    int e   = blockIdx.z;
    int cnt = g_counts[e];
    int m0  = blockIdx.y * BM;
    if (m0 >= cnt) return;
    int n0  = blockIdx.x * BN;
    int tid = threadIdx.x, lane = tid & 31, wid = tid >> 5;
    int wr = wid >> 2, wc = wid & 3;
    int row = tid >> 1, half = tid & 1;

    int arow = m0 + row; if (arow >= cnt) arow = cnt - 1;
    int brow = n0 + row;
    RowPtrs rp;
    rp.ah = (const uint4*)(g_Hhi + ((size_t)e * MAXP + arow) * F_DIM);
    rp.al = (const uint4*)(g_Hlo + ((size_t)e * MAXP + arow) * F_DIM);
    rp.bh = (const uint4*)(g_W2hi + ((size_t)e * D_MODEL + brow) * F_DIM);
    rp.bl = (const uint4*)(g_W2lo + ((size_t)e * D_MODEL + brow) * F_DIM);

    float c[4][4][4];
#pragma unroll
    for (int i = 0; i < 4; i++)
#pragma unroll
        for (int j = 0; j < 4; j++)
#pragma unroll
            for (int k = 0; k < 4; k++) c[i][j][k] = 0.f;

    run_mainloop(tiles, smbase, rp, F_DIM / BK, wr, wc, lane, c, row, half);

    // epilogue: (acc + bias) * wt -> g_O (fp32)
    int lrow = lane >> 2, lcol2 = (lane & 3) * 2;
#pragma unroll
    for (int nt = 0; nt < 4; nt++) {
        int col = n0 + wc * 32 + nt * 8 + lcol2;
        float bb0 = b2[e * D_MODEL + col];
        float bb1 = b2[e * D_MODEL + col + 1];
#pragma unroll
        for (int mt = 0; mt < 4; mt++) {
            int r0 = m0 + wr * 64 + mt * 16 + lrow;
#pragma unroll
            for (int h = 0; h < 2; h++) {
                int r = r0 + h * 8;
                if (r < cnt) {
                    float wt = g_wt[e * MAXP + r];
                    float2 o;
                    o.x = (c[mt][nt][h * 2 + 0] + bb0) * wt;
                    o.y = (c[mt][nt][h * 2 + 1] + bb1) * wt;
                    *(float2*)(g_O + ((size_t)e * MAXP + r) * D_MODEL + col) = o;
                }
            }
        }
    }
}

// ---------------------------------------------------------------------------
__global__ void ln_kernel(const float* __restrict__ x,
                          const float* __restrict__ gamma,
                          const float* __restrict__ beta,
                          float* __restrict__ out) {
    int t   = blockIdx.x;
    int tid = threadIdx.x;
    int s0 = g_slot[t * 2 + 0];
    int s1 = g_slot[t * 2 + 1];

    const float4* xr = (const float4*)(x + (size_t)t * D_MODEL);
    const float4* o0 = (const float4*)(g_O + (size_t)s0 * D_MODEL);
    const float4* o1 = (const float4*)(g_O + (size_t)s1 * D_MODEL);

    float4 xv = xr[tid];
    float4 a  = o0[tid];
    float4 b  = o1[tid];
    float4 y;
    y.x = xv.x + a.x + b.x;
    y.y = xv.y + a.y + b.y;
    y.z = xv.z + a.z + b.z;
    y.w = xv.w + a.w + b.w;

    float s  = y.x + y.y + y.z + y.w;
    float sq = y.x * y.x + y.y * y.y + y.z * y.z + y.w * y.w;
#pragma unroll
    for (int off = 16; off > 0; off >>= 1) {
        s  += __shfl_down_sync(0xffffffffu, s,  off);
        sq += __shfl_down_sync(0xffffffffu, sq, off);
    }
    int warp = tid >> 5, lane = tid & 31;
    __shared__ float ws[8], wq[8], red[2];
    if (lane == 0) { ws[warp] = s; wq[warp] = sq; }
    __syncthreads();
    if (tid == 0) {
        float ts = 0.f, tq = 0.f;
#pragma unroll
        for (int i = 0; i < 8; i++) { ts += ws[i]; tq += wq[i]; }
        red[0] = ts; red[1] = tq;
    }
    __syncthreads();

    float mu  = red[0] * (1.0f / D_MODEL);
    float var = red[1] * (1.0f / D_MODEL) - mu * mu;
    float inv = rsqrtf(var + LN_EPS);

    float4 g  = ((const float4*)gamma)[tid];
    float4 bt = ((const float4*)beta)[tid];
    float4 o;
    o.x = g.x * (y.x - mu) * inv + bt.x;
    o.y = g.y * (y.y - mu) * inv + bt.y;
    o.z = g.z * (y.z - mu) * inv + bt.z;
    o.w = g.w * (y.w - mu) * inv + bt.w;
    ((float4*)out)[(size_t)t * (D_MODEL / 4) + tid] = o;
}

// ---------------------------------------------------------------------------
extern "C" void kernel_launch(void* const* d_in, const int* in_sizes, int n_in,
                              void* d_out, int out_size) {
    const float* x     = (const float*)d_in[0];
    const float* Wg    = (const float*)d_in[1];
    const float* bg    = (const float*)d_in[2];
    const float* W1    = (const float*)d_in[3];
    const float* b1    = (const float*)d_in[4];
    const float* W2    = (const float*)d_in[5];
    const float* b2    = (const float*)d_in[6];
    const float* gamma = (const float*)d_in[7];
    const float* beta  = (const float*)d_in[8];
    float* out = (float*)d_out;

    cudaFuncSetAttribute(gemm1_mma, cudaFuncAttributeMaxDynamicSharedMemorySize, SMEM_BYTES);
    cudaFuncSetAttribute(gemm2_mma, cudaFuncAttributeMaxDynamicSharedMemorySize, SMEM_BYTES);

    init_kernel<<<1, 32>>>();
    gating_kernel<<<T_TOKENS / 8, 256>>>(x, Wg, bg);
    convert_x_kernel<<<T_TOKENS * D_MODEL / 4 / 256, 256>>>(x);
    transpose_w1_kernel<<<dim3(F_DIM / 32, D_MODEL / 32, N_EXP), dim3(32, 8)>>>(W1);
    transpose_w2_kernel<<<dim3(D_MODEL / 32, F_DIM / 32, N_EXP), dim3(32, 8)>>>(W2);

    gemm1_mma<<<dim3(F_DIM / BN, MAXP / BM, N_EXP), 256, SMEM_BYTES>>>(b1);
    gemm2_mma<<<dim3(D_MODEL / BN, MAXP / BM, N_EXP), 256, SMEM_BYTES>>>(b2);

    ln_kernel<<<T_TOKENS, 256>>>(x, gamma, beta, out);
}

// round 8
// speedup vs baseline: 4.2789x; 2.2569x over previous
#include <cuda_runtime.h>
#include <cuda_fp16.h>
#include <stdint.h>
#include <math.h>

#define T_TOKENS 4096
#define D_MODEL  1024
#define N_EXP    8
#define F_DIM    2048
#define LN_EPS   1e-5f
#define MAXP     4096

// tiles
#define BM 128
#define BN 128
#define BK 32
#define STAGES 3
#define ROWB 80                         // 64B data + 16B pad: 20-word stride, conflict-free
#define BUFB (128 * ROWB)               // 10240 bytes per operand buffer
#define A_OFF 0
#define B_OFF BUFB
#define STG_BYTES (2 * BUFB)            // 20480 per stage
#define SMEM_BYTES (STAGES * STG_BYTES) // 61440 dynamic -> 2 CTAs/SM

__device__ __forceinline__ void mma16816(float* c, const uint32_t* a, const uint32_t* b) {
    asm volatile(
        "mma.sync.aligned.m16n8k16.row.col.f32.f16.f16.f32 "
        "{%0,%1,%2,%3}, {%4,%5,%6,%7}, {%8,%9}, {%0,%1,%2,%3};"
        : "+f"(c[0]), "+f"(c[1]), "+f"(c[2]), "+f"(c[3])
        : "r"(a[0]), "r"(a[1]), "r"(a[2]), "r"(a[3]), "r"(b[0]), "r"(b[1]));
}
__device__ __forceinline__ uint32_t smem_u32(const void* p) {
    uint32_t a;
    asm("{ .reg .u64 t; cvta.to.shared.u64 t, %1; cvt.u32.u64 %0, t; }"
        : "=r"(a) : "l"(p));
    return a;
}
__device__ __forceinline__ void cp16(uint32_t saddr, const void* g) {
    asm volatile("cp.async.cg.shared.global [%0], [%1], 16;"
                 :: "r"(saddr), "l"(g) : "memory");
}
#define CP_COMMIT() asm volatile("cp.async.commit_group;" ::: "memory")
#define CP_WAIT1()  asm volatile("cp.async.wait_group 1;" ::: "memory")

// ---------------- scratch ----------------
__device__ int   g_counts[N_EXP];
__device__ int   g_tok[N_EXP * MAXP];
__device__ float g_wt[N_EXP * MAXP];
__device__ int   g_slot[T_TOKENS * 2];
__device__ __align__(16) __half g_x16[(size_t)T_TOKENS * D_MODEL];
__device__ __align__(16) __half g_W1t[(size_t)N_EXP * F_DIM * D_MODEL]; // [e][f][d]
__device__ __align__(16) __half g_W2t[(size_t)N_EXP * D_MODEL * F_DIM]; // [e][d][f]
__device__ __align__(16) __half g_H16[(size_t)N_EXP * MAXP * F_DIM];
__device__ __align__(16) float  g_O[(size_t)N_EXP * MAXP * D_MODEL];

// ---------------------------------------------------------------------------
__global__ void init_kernel() {
    if (threadIdx.x < N_EXP) g_counts[threadIdx.x] = 0;
}

// ---------------------------------------------------------------------------
__global__ void gating_kernel(const float* __restrict__ x,
                              const float* __restrict__ Wg,
                              const float* __restrict__ bg) {
    int warp = threadIdx.x >> 5;
    int lane = threadIdx.x & 31;
    int t = blockIdx.x * 8 + warp;
    if (t >= T_TOKENS) return;

    float acc[8];
#pragma unroll
    for (int e = 0; e < 8; e++) acc[e] = 0.f;
    const float* xr = x + (size_t)t * D_MODEL;
    for (int k = lane; k < D_MODEL; k += 32) {
        float xv = xr[k];
        float4 w0 = *(const float4*)(Wg + (size_t)k * 8);
        float4 w1 = *(const float4*)(Wg + (size_t)k * 8 + 4);
        acc[0] += xv * w0.x; acc[1] += xv * w0.y;
        acc[2] += xv * w0.z; acc[3] += xv * w0.w;
        acc[4] += xv * w1.x; acc[5] += xv * w1.y;
        acc[6] += xv * w1.z; acc[7] += xv * w1.w;
    }
#pragma unroll
    for (int e = 0; e < 8; e++)
#pragma unroll
        for (int off = 16; off > 0; off >>= 1)
            acc[e] += __shfl_down_sync(0xffffffffu, acc[e], off);

    if (lane == 0) {
        float v[8];
#pragma unroll
        for (int e = 0; e < 8; e++) v[e] = acc[e] + bg[e];
        int b0 = 0; float m0 = v[0];
#pragma unroll
        for (int e = 1; e < 8; e++) if (v[e] > m0) { m0 = v[e]; b0 = e; }
        int b1i = (b0 == 0) ? 1 : 0; float m1 = v[b1i];
#pragma unroll
        for (int e = 0; e < 8; e++)
            if (e != b0 && v[e] > m1) { m1 = v[e]; b1i = e; }

        float ex = expf(m1 - m0);
        float s  = 1.0f + ex;
        int p0 = atomicAdd(&g_counts[b0], 1);
        g_tok[b0 * MAXP + p0] = t;
        g_wt [b0 * MAXP + p0] = 1.0f / s;
        g_slot[t * 2 + 0] = b0 * MAXP + p0;
        int p1 = atomicAdd(&g_counts[b1i], 1);
        g_tok[b1i * MAXP + p1] = t;
        g_wt [b1i * MAXP + p1] = ex / s;
        g_slot[t * 2 + 1] = b1i * MAXP + p1;
    }
}

// ---------------------------------------------------------------------------
// fp32 -> fp16 conversion of x (globals referenced in DEVICE code)
__global__ void convert_x_kernel(const float* __restrict__ x) {
    int i = blockIdx.x * blockDim.x + threadIdx.x;   // group of 4 elements
    float4 v = ((const float4*)x)[i];
    __half2 a = __floats2half2_rn(v.x, v.y);
    __half2 b = __floats2half2_rn(v.z, v.w);
    ((__half2*)g_x16)[i * 2 + 0] = a;
    ((__half2*)g_x16)[i * 2 + 1] = b;
}

// ---------------------------------------------------------------------------
// W [E][R][C] fp32 -> fp16 [E][C][R].
// Output pointer MUST be a device-resolved symbol (GB300 ATS: host-shadow
// addresses silently write host memory — the R3-R5 zero-weights bug).
__device__ __forceinline__ void transpose_body(const float* __restrict__ W,
                                               __half* __restrict__ dst,
                                               int R, int C) {
    __shared__ float t[32][33];
    int e  = blockIdx.z;
    int c0 = blockIdx.x * 32, r0 = blockIdx.y * 32;
    int tx = threadIdx.x, ty = threadIdx.y;
    const float* Wp = W + (size_t)e * R * C;
#pragma unroll
    for (int i = 0; i < 32; i += 8)
        t[ty + i][tx] = Wp[(size_t)(r0 + ty + i) * C + (c0 + tx)];
    __syncthreads();
    size_t ob = (size_t)e * C * R;
#pragma unroll
    for (int i = 0; i < 32; i += 8) {
        size_t o = ob + (size_t)(c0 + ty + i) * R + (r0 + tx);
        dst[o] = __float2half_rn(t[tx][ty + i]);
    }
}
__global__ void transpose_w1_kernel(const float* __restrict__ W) {
    transpose_body(W, g_W1t, D_MODEL, F_DIM);
}
__global__ void transpose_w2_kernel(const float* __restrict__ W) {
    transpose_body(W, g_W2t, F_DIM, D_MODEL);
}

// ---------------------------------------------------------------------------
// HMMA mainloop, cp.async 3-stage pipelined, fp16 single-pass.
// smem writer contract: element (row, k_local) of each operand buffer lives at
//   stage_base + buf_off + row*ROWB + 2*k_local
struct RowPtrs {
    const uint4* a;
    const uint4* b;
};

__device__ __forceinline__ void cp_stage(uint32_t smbase, const RowPtrs& rp,
                                         int s, int kt, int row, int half) {
    uint32_t off = (uint32_t)row * ROWB + (uint32_t)half * 32u;
    uint32_t b   = smbase + s * STG_BYTES + off;
    int idx = kt * 4 + half * 2;
    cp16(b + A_OFF,      rp.a + idx);
    cp16(b + A_OFF + 16, rp.a + idx + 1);
    cp16(b + B_OFF,      rp.b + idx);
    cp16(b + B_OFF + 16, rp.b + idx + 1);
}

// Per the PTX ISA m16n8k16 fragment tables (verified in R6/R7):
//   A: a0=(row,k) a1=(row+8,k) a2=(row,k+8) a3=(row+8,k+8),
//      row = wtile_m + (lane>>2), k = khalf*16 + (lane&3)*2
//   B: b0=(k..k+1, n) b1=(k+8..k+9, n),  n = wtile_n + (lane>>2)
__device__ __forceinline__ void compute_tiles(const char* tiles, int wr, int wc,
                                              int lane, float c[4][4][4]) {
    uint32_t arow0 = (uint32_t)(wr * 64 + (lane >> 2)) * ROWB;
    uint32_t brow0 = (uint32_t)(wc * 32 + (lane >> 2)) * ROWB;
    uint32_t kb    = (uint32_t)(lane & 3) * 4u;
#pragma unroll
    for (int kk = 0; kk < 2; kk++) {
        uint32_t ko = (uint32_t)kk * 32u + kb;
        uint32_t a[4][4], b[4][2];
#pragma unroll
        for (int mt = 0; mt < 4; mt++) {
            const char* r0 = tiles + A_OFF + arow0 + (uint32_t)(mt * 16) * ROWB + ko;
            a[mt][0] = *(const uint32_t*)(r0);
            a[mt][1] = *(const uint32_t*)(r0 + 8 * ROWB);
            a[mt][2] = *(const uint32_t*)(r0 + 16);
            a[mt][3] = *(const uint32_t*)(r0 + 8 * ROWB + 16);
        }
#pragma unroll
        for (int nt = 0; nt < 4; nt++) {
            const char* r0 = tiles + B_OFF + brow0 + (uint32_t)(nt * 8) * ROWB + ko;
            b[nt][0] = *(const uint32_t*)(r0);
            b[nt][1] = *(const uint32_t*)(r0 + 16);
        }
#pragma unroll
        for (int mt = 0; mt < 4; mt++)
#pragma unroll
            for (int nt = 0; nt < 4; nt++)
                mma16816(c[mt][nt], a[mt], b[nt]);
    }
}

// One barrier per k-tile (trailing sync provably redundant, see R7).
__device__ __forceinline__ void run_mainloop(char* tiles, uint32_t smbase,
                                             const RowPtrs& rp, int ktiles,
                                             int wr, int wc, int lane,
                                             float c[4][4][4], int row, int half) {
#pragma unroll
    for (int s = 0; s < STAGES - 1; s++) {
        cp_stage(smbase, rp, s, s, row, half);
        CP_COMMIT();
    }
    for (int kt = 0; kt < ktiles; kt++) {
        CP_WAIT1();
        __syncthreads();
        int kn = kt + STAGES - 1;
        if (kn < ktiles) cp_stage(smbase, rp, kn % STAGES, kn, row, half);
        CP_COMMIT();
        compute_tiles(tiles + (kt % STAGES) * STG_BYTES, wr, wc, lane, c);
    }
}

// ---------------------------------------------------------------------------
// GEMM1: H[e-rows, F] = relu( Xg @ W1t[e] + b1[e] ), fp16 single-pass
__global__ void __launch_bounds__(256, 2)
gemm1_mma(const float* __restrict__ b1) {
    extern __shared__ __align__(16) char tiles[];
    uint32_t smbase = smem_u32(tiles);
    int e   = blockIdx.z;
    int cnt = g_counts[e];
    int m0  = blockIdx.y * BM;
    if (m0 >= cnt) return;
    int n0  = blockIdx.x * BN;
    int tid = threadIdx.x, lane = tid & 31, wid = tid >> 5;
    int wr = wid >> 2, wc = wid & 3;
    int row = tid >> 1, half = tid & 1;

    int arow = m0 + row; if (arow >= cnt) arow = cnt - 1;
    int tok  = g_tok[e * MAXP + arow];
    int brow = n0 + row;
    RowPtrs rp;
    rp.a = (const uint4*)(g_x16 + (size_t)tok * D_MODEL);
    rp.b = (const uint4*)(g_W1t + ((size_t)e * F_DIM + brow) * D_MODEL);

    float c[4][4][4];
#pragma unroll
    for (int i = 0; i < 4; i++)
#pragma unroll
        for (int j = 0; j < 4; j++)
#pragma unroll
            for (int k = 0; k < 4; k++) c[i][j][k] = 0.f;

    run_mainloop(tiles, smbase, rp, D_MODEL / BK, wr, wc, lane, c, row, half);

    // epilogue: bias + relu -> fp16 g_H16 (register-direct)
    int lrow = lane >> 2, lcol2 = (lane & 3) * 2;
#pragma unroll
    for (int nt = 0; nt < 4; nt++) {
        int col = n0 + wc * 32 + nt * 8 + lcol2;
        float bb0 = b1[e * F_DIM + col];
        float bb1 = b1[e * F_DIM + col + 1];
#pragma unroll
        for (int mt = 0; mt < 4; mt++) {
            int r0 = m0 + wr * 64 + mt * 16 + lrow;
#pragma unroll
            for (int h = 0; h < 2; h++) {
                int r = r0 + h * 8;
                if (r < cnt) {
                    float v0 = fmaxf(c[mt][nt][h * 2 + 0] + bb0, 0.f);
                    float v1 = fmaxf(c[mt][nt][h * 2 + 1] + bb1, 0.f);
                    size_t o = ((size_t)e * MAXP + r) * F_DIM + col;
                    *(__half2*)(g_H16 + o) = __floats2half2_rn(v0, v1);
                }
            }
        }
    }
}

// ---------------------------------------------------------------------------
// GEMM2: O[e-rows, D] = wt * ( H @ W2t[e] + b2[e] )
__global__ void __launch_bounds__(256, 2)
gemm2_mma(const float* __restrict__ b2) {
    extern __shared__ __align__(16) char tiles[];
    uint32_t smbase = smem_u32(tiles);
    int e   = blockIdx.z;
    int cnt = g_counts[e];
    int m0  = blockIdx.y * BM;
    if (m0 >= cnt) return;
    int n0  = blockIdx.x * BN;
    int tid = threadIdx.x, lane = tid & 31, wid = tid >> 5;
    int wr = wid >> 2, wc = wid & 3;
    int row = tid >> 1, half = tid & 1;

    int arow = m0 + row; if (arow >= cnt) arow = cnt - 1;
    int brow = n0 + row;
    RowPtrs rp;
    rp.a = (const uint4*)(g_H16 + ((size_t)e * MAXP + arow) * F_DIM);
    rp.b = (const uint4*)(g_W2t + ((size_t)e * D_MODEL + brow) * F_DIM);

    float c[4][4][4];
#pragma unroll
    for (int i = 0; i < 4; i++)
#pragma unroll
        for (int j = 0; j < 4; j++)
#pragma unroll
            for (int k = 0; k < 4; k++) c[i][j][k] = 0.f;

    run_mainloop(tiles, smbase, rp, F_DIM / BK, wr, wc, lane, c, row, half);

    // epilogue: (acc + bias) * wt -> g_O (fp32)
    int lrow = lane >> 2, lcol2 = (lane & 3) * 2;
#pragma unroll
    for (int nt = 0; nt < 4; nt++) {
        int col = n0 + wc * 32 + nt * 8 + lcol2;
        float bb0 = b2[e * D_MODEL + col];
        float bb1 = b2[e * D_MODEL + col + 1];
#pragma unroll
        for (int mt = 0; mt < 4; mt++) {
            int r0 = m0 + wr * 64 + mt * 16 + lrow;
#pragma unroll
            for (int h = 0; h < 2; h++) {
                int r = r0 + h * 8;
                if (r < cnt) {
                    float wt = g_wt[e * MAXP + r];
                    float2 o;
                    o.x = (c[mt][nt][h * 2 + 0] + bb0) * wt;
                    o.y = (c[mt][nt][h * 2 + 1] + bb1) * wt;
                    *(float2*)(g_O + ((size_t)e * MAXP + r) * D_MODEL + col) = o;
                }
            }
        }
    }
}

// ---------------------------------------------------------------------------
__global__ void ln_kernel(const float* __restrict__ x,
                          const float* __restrict__ gamma,
                          const float* __restrict__ beta,
                          float* __restrict__ out) {
    int t   = blockIdx.x;
    int tid = threadIdx.x;
    int s0 = g_slot[t * 2 + 0];
    int s1 = g_slot[t * 2 + 1];

    const float4* xr = (const float4*)(x + (size_t)t * D_MODEL);
    const float4* o0 = (const float4*)(g_O + (size_t)s0 * D_MODEL);
    const float4* o1 = (const float4*)(g_O + (size_t)s1 * D_MODEL);

    float4 xv = xr[tid];
    float4 a  = o0[tid];
    float4 b  = o1[tid];
    float4 y;
    y.x = xv.x + a.x + b.x;
    y.y = xv.y + a.y + b.y;
    y.z = xv.z + a.z + b.z;
    y.w = xv.w + a.w + b.w;

    float s  = y.x + y.y + y.z + y.w;
    float sq = y.x * y.x + y.y * y.y + y.z * y.z + y.w * y.w;
#pragma unroll
    for (int off = 16; off > 0; off >>= 1) {
        s  += __shfl_down_sync(0xffffffffu, s,  off);
        sq += __shfl_down_sync(0xffffffffu, sq, off);
    }
    int warp = tid >> 5, lane = tid & 31;
    __shared__ float ws[8], wq[8], red[2];
    if (lane == 0) { ws[warp] = s; wq[warp] = sq; }
    __syncthreads();
    if (tid == 0) {
        float ts = 0.f, tq = 0.f;
#pragma unroll
        for (int i = 0; i < 8; i++) { ts += ws[i]; tq += wq[i]; }
        red[0] = ts; red[1] = tq;
    }
    __syncthreads();

    float mu  = red[0] * (1.0f / D_MODEL);
    float var = red[1] * (1.0f / D_MODEL) - mu * mu;
    float inv = rsqrtf(var + LN_EPS);

    float4 g  = ((const float4*)gamma)[tid];
    float4 bt = ((const float4*)beta)[tid];
    float4 o;
    o.x = g.x * (y.x - mu) * inv + bt.x;
    o.y = g.y * (y.y - mu) * inv + bt.y;
    o.z = g.z * (y.z - mu) * inv + bt.z;
    o.w = g.w * (y.w - mu) * inv + bt.w;
    ((float4*)out)[(size_t)t * (D_MODEL / 4) + tid] = o;
}

// ---------------------------------------------------------------------------
extern "C" void kernel_launch(void* const* d_in, const int* in_sizes, int n_in,
                              void* d_out, int out_size) {
    const float* x     = (const float*)d_in[0];
    const float* Wg    = (const float*)d_in[1];
    const float* bg    = (const float*)d_in[2];
    const float* W1    = (const float*)d_in[3];
    const float* b1    = (const float*)d_in[4];
    const float* W2    = (const float*)d_in[5];
    const float* b2    = (const float*)d_in[6];
    const float* gamma = (const float*)d_in[7];
    const float* beta  = (const float*)d_in[8];
    float* out = (float*)d_out;

    cudaFuncSetAttribute(gemm1_mma, cudaFuncAttributeMaxDynamicSharedMemorySize, SMEM_BYTES);
    cudaFuncSetAttribute(gemm2_mma, cudaFuncAttributeMaxDynamicSharedMemorySize, SMEM_BYTES);

    init_kernel<<<1, 32>>>();
    gating_kernel<<<T_TOKENS / 8, 256>>>(x, Wg, bg);
    convert_x_kernel<<<T_TOKENS * D_MODEL / 4 / 256, 256>>>(x);
    transpose_w1_kernel<<<dim3(F_DIM / 32, D_MODEL / 32, N_EXP), dim3(32, 8)>>>(W1);
    transpose_w2_kernel<<<dim3(D_MODEL / 32, F_DIM / 32, N_EXP), dim3(32, 8)>>>(W2);

    gemm1_mma<<<dim3(F_DIM / BN, MAXP / BM, N_EXP), 256, SMEM_BYTES>>>(b1);
    gemm2_mma<<<dim3(D_MODEL / BN, MAXP / BM, N_EXP), 256, SMEM_BYTES>>>(b2);

    ln_kernel<<<T_TOKENS, 256>>>(x, gamma, beta, out);
}

// round 9
// speedup vs baseline: 5.0942x; 1.1905x over previous
#include <cuda_runtime.h>
#include <cuda_fp16.h>
#include <stdint.h>
#include <math.h>

#define T_TOKENS 4096
#define D_MODEL  1024
#define N_EXP    8
#define F_DIM    2048
#define LN_EPS   1e-5f
#define MAXP     4096

// tiles
#define BM 128
#define BN 128
#define BK 32
#define STAGES 3
#define ROWB 80                         // 64B data + 16B pad: 20-word stride, conflict-free
#define BUFB (128 * ROWB)               // 10240 bytes per operand buffer
#define A_OFF 0
#define B_OFF BUFB
#define STG_BYTES (2 * BUFB)            // 20480 per stage
#define SMEM_BYTES (STAGES * STG_BYTES) // 61440 dynamic -> 2 CTAs/SM

__device__ __forceinline__ void mma16816(float* c, const uint32_t* a, const uint32_t* b) {
    asm volatile(
        "mma.sync.aligned.m16n8k16.row.col.f32.f16.f16.f32 "
        "{%0,%1,%2,%3}, {%4,%5,%6,%7}, {%8,%9}, {%0,%1,%2,%3};"
        : "+f"(c[0]), "+f"(c[1]), "+f"(c[2]), "+f"(c[3])
        : "r"(a[0]), "r"(a[1]), "r"(a[2]), "r"(a[3]), "r"(b[0]), "r"(b[1]));
}
__device__ __forceinline__ uint32_t smem_u32(const void* p) {
    uint32_t a;
    asm("{ .reg .u64 t; cvta.to.shared.u64 t, %1; cvt.u32.u64 %0, t; }"
        : "=r"(a) : "l"(p));
    return a;
}
__device__ __forceinline__ void cp16(uint32_t saddr, const void* g) {
    asm volatile("cp.async.cg.shared.global [%0], [%1], 16;"
                 :: "r"(saddr), "l"(g) : "memory");
}
#define CP_COMMIT() asm volatile("cp.async.commit_group;" ::: "memory")
#define CP_WAIT1()  asm volatile("cp.async.wait_group 1;" ::: "memory")

// ldmatrix.x4: returns the 4 address-group 8x8 matrices in r0..r3.
__device__ __forceinline__ void ldsm4(uint32_t* r, uint32_t addr) {
    asm volatile("ldmatrix.sync.aligned.m8n8.x4.shared.b16 {%0,%1,%2,%3}, [%4];"
                 : "=r"(r[0]), "=r"(r[1]), "=r"(r[2]), "=r"(r[3]) : "r"(addr));
}

// ---------------- scratch ----------------
__device__ int   g_counts[N_EXP];
__device__ int   g_tok[N_EXP * MAXP];
__device__ float g_wt[N_EXP * MAXP];
__device__ int   g_slot[T_TOKENS * 2];
__device__ __align__(16) __half g_x16[(size_t)T_TOKENS * D_MODEL];
__device__ __align__(16) __half g_W1t[(size_t)N_EXP * F_DIM * D_MODEL]; // [e][f][d]
__device__ __align__(16) __half g_W2t[(size_t)N_EXP * D_MODEL * F_DIM]; // [e][d][f]
__device__ __align__(16) __half g_H16[(size_t)N_EXP * MAXP * F_DIM];
__device__ __align__(16) float  g_O[(size_t)N_EXP * MAXP * D_MODEL];

// ---------------------------------------------------------------------------
__global__ void init_kernel() {
    if (threadIdx.x < N_EXP) g_counts[threadIdx.x] = 0;
}

// ---------------------------------------------------------------------------
__global__ void gating_kernel(const float* __restrict__ x,
                              const float* __restrict__ Wg,
                              const float* __restrict__ bg) {
    int warp = threadIdx.x >> 5;
    int lane = threadIdx.x & 31;
    int t = blockIdx.x * 8 + warp;
    if (t >= T_TOKENS) return;

    float acc[8];
#pragma unroll
    for (int e = 0; e < 8; e++) acc[e] = 0.f;
    const float* xr = x + (size_t)t * D_MODEL;
    for (int k = lane; k < D_MODEL; k += 32) {
        float xv = xr[k];
        float4 w0 = *(const float4*)(Wg + (size_t)k * 8);
        float4 w1 = *(const float4*)(Wg + (size_t)k * 8 + 4);
        acc[0] += xv * w0.x; acc[1] += xv * w0.y;
        acc[2] += xv * w0.z; acc[3] += xv * w0.w;
        acc[4] += xv * w1.x; acc[5] += xv * w1.y;
        acc[6] += xv * w1.z; acc[7] += xv * w1.w;
    }
#pragma unroll
    for (int e = 0; e < 8; e++)
#pragma unroll
        for (int off = 16; off > 0; off >>= 1)
            acc[e] += __shfl_down_sync(0xffffffffu, acc[e], off);

    if (lane == 0) {
        float v[8];
#pragma unroll
        for (int e = 0; e < 8; e++) v[e] = acc[e] + bg[e];
        int b0 = 0; float m0 = v[0];
#pragma unroll
        for (int e = 1; e < 8; e++) if (v[e] > m0) { m0 = v[e]; b0 = e; }
        int b1i = (b0 == 0) ? 1 : 0; float m1 = v[b1i];
#pragma unroll
        for (int e = 0; e < 8; e++)
            if (e != b0 && v[e] > m1) { m1 = v[e]; b1i = e; }

        float ex = expf(m1 - m0);
        float s  = 1.0f + ex;
        int p0 = atomicAdd(&g_counts[b0], 1);
        g_tok[b0 * MAXP + p0] = t;
        g_wt [b0 * MAXP + p0] = 1.0f / s;
        g_slot[t * 2 + 0] = b0 * MAXP + p0;
        int p1 = atomicAdd(&g_counts[b1i], 1);
        g_tok[b1i * MAXP + p1] = t;
        g_wt [b1i * MAXP + p1] = ex / s;
        g_slot[t * 2 + 1] = b1i * MAXP + p1;
    }
}

// ---------------------------------------------------------------------------
// fp32 -> fp16 conversion of x (globals referenced in DEVICE code)
__global__ void convert_x_kernel(const float* __restrict__ x) {
    int i = blockIdx.x * blockDim.x + threadIdx.x;   // group of 4 elements
    float4 v = ((const float4*)x)[i];
    __half2 a = __floats2half2_rn(v.x, v.y);
    __half2 b = __floats2half2_rn(v.z, v.w);
    ((__half2*)g_x16)[i * 2 + 0] = a;
    ((__half2*)g_x16)[i * 2 + 1] = b;
}

// ---------------------------------------------------------------------------
// W [E][R][C] fp32 -> fp16 [E][C][R], half2 (4B) stores for coalescing.
// Output pointer MUST be a device-resolved symbol (GB300 ATS: host-shadow
// addresses silently write host memory — the R3-R5 zero-weights bug).
__device__ __forceinline__ void transpose_body(const float* __restrict__ W,
                                               __half* __restrict__ dst,
                                               int R, int C) {
    __shared__ float t[64][33];
    int e  = blockIdx.z;
    int c0 = blockIdx.x * 32, r0 = blockIdx.y * 64;
    int tx = threadIdx.x, ty = threadIdx.y;
    const float* Wp = W + (size_t)e * R * C;
#pragma unroll
    for (int i = 0; i < 8; i++)
        t[ty + i * 8][tx] = Wp[(size_t)(r0 + ty + i * 8) * C + (c0 + tx)];
    __syncthreads();
    size_t ob = (size_t)e * C * R;
#pragma unroll
    for (int i = 0; i < 4; i++) {
        int c = ty + i * 8;   // 0..31
        __half2 v = __floats2half2_rn(t[tx * 2][c], t[tx * 2 + 1][c]);
        *(__half2*)(dst + ob + (size_t)(c0 + c) * R + r0 + tx * 2) = v;
    }
}
__global__ void transpose_w1_kernel(const float* __restrict__ W) {
    transpose_body(W, g_W1t, D_MODEL, F_DIM);
}
__global__ void transpose_w2_kernel(const float* __restrict__ W) {
    transpose_body(W, g_W2t, F_DIM, D_MODEL);
}

// ---------------------------------------------------------------------------
// HMMA mainloop, cp.async 3-stage pipelined, fp16 single-pass, ldmatrix loads.
// smem writer contract: element (row, k_local) of each operand buffer lives at
//   stage_base + buf_off + row*ROWB + 2*k_local
struct RowPtrs {
    const uint4* a;
    const uint4* b;
};

__device__ __forceinline__ void cp_stage(uint32_t smbase, const RowPtrs& rp,
                                         int s, int kt, int row, int half) {
    uint32_t off = (uint32_t)row * ROWB + (uint32_t)half * 32u;
    uint32_t b   = smbase + s * STG_BYTES + off;
    int idx = kt * 4 + half * 2;
    cp16(b + A_OFF,      rp.a + idx);
    cp16(b + A_OFF + 16, rp.a + idx + 1);
    cp16(b + B_OFF,      rp.b + idx);
    cp16(b + B_OFF + 16, rp.b + idx + 1);
}

// ldmatrix address groups (verified equivalent to the R6/R8 manual loads):
//   A (m16k16, rows=m):  g0 rows m..m+7 @k | g1 rows m+8..15 @k
//                        g2 rows m..m+7 @k+8 | g3 rows m+8..15 @k+8
//     -> r0..r3 = a0..a3 exactly per the PTX mma fragment table.
//   B (rows=n, x4 covers n..n+15): g0 n..n+7 @k | g1 n..n+7 @k+8
//                                  g2 n+8..15 @k | g3 n+8..15 @k+8
//     -> {r0,r1} = (b0,b1) for n-octet 0, {r2,r3} for n-octet 1.
__device__ __forceinline__ void compute_tiles(uint32_t sbase,
                                              const uint32_t aoff[4],
                                              const uint32_t boff[2],
                                              float c[4][4][4]) {
#pragma unroll
    for (int kk = 0; kk < 2; kk++) {
        uint32_t ko = (uint32_t)kk * 32u;
        uint32_t a[4][4], b[2][4];
#pragma unroll
        for (int mt = 0; mt < 4; mt++)
            ldsm4(a[mt], sbase + A_OFF + aoff[mt] + ko);
#pragma unroll
        for (int p = 0; p < 2; p++)
            ldsm4(b[p], sbase + B_OFF + boff[p] + ko);
#pragma unroll
        for (int mt = 0; mt < 4; mt++)
#pragma unroll
            for (int nt = 0; nt < 4; nt++)
                mma16816(c[mt][nt], a[mt], &b[nt >> 1][(nt & 1) * 2]);
    }
}

// One barrier per k-tile (trailing sync provably redundant, see R7).
__device__ __forceinline__ void run_mainloop(uint32_t smbase,
                                             const RowPtrs& rp, int ktiles,
                                             const uint32_t aoff[4],
                                             const uint32_t boff[2],
                                             float c[4][4][4], int row, int half) {
#pragma unroll
    for (int s = 0; s < STAGES - 1; s++) {
        cp_stage(smbase, rp, s, s, row, half);
        CP_COMMIT();
    }
    for (int kt = 0; kt < ktiles; kt++) {
        CP_WAIT1();
        __syncthreads();
        int kn = kt + STAGES - 1;
        if (kn < ktiles) cp_stage(smbase, rp, kn % STAGES, kn, row, half);
        CP_COMMIT();
        compute_tiles(smbase + (kt % STAGES) * STG_BYTES, aoff, boff, c);
    }
}

// lane offsets for ldmatrix (relative to operand buffer base)
__device__ __forceinline__ void make_offsets(int wr, int wc, int lane,
                                             uint32_t aoff[4], uint32_t boff[2]) {
#pragma unroll
    for (int mt = 0; mt < 4; mt++)
        aoff[mt] = (uint32_t)(wr * 64 + mt * 16 + (lane & 15)) * ROWB
                 + (uint32_t)(lane >> 4) * 16u;
#pragma unroll
    for (int p = 0; p < 2; p++)
        boff[p] = (uint32_t)(wc * 32 + p * 16 + ((lane >> 4) << 3) + (lane & 7)) * ROWB
                + (uint32_t)((lane >> 3) & 1) * 16u;
}

// ---------------------------------------------------------------------------
// GEMM1: H[e-rows, F] = relu( Xg @ W1t[e] + b1[e] ), fp16 single-pass
__global__ void __launch_bounds__(256, 2)
gemm1_mma(const float* __restrict__ b1) {
    extern __shared__ __align__(16) char tiles[];
    uint32_t smbase = smem_u32(tiles);
    int e   = blockIdx.z;
    int cnt = g_counts[e];
    int m0  = blockIdx.y * BM;
    if (m0 >= cnt) return;
    int n0  = blockIdx.x * BN;
    int tid = threadIdx.x, lane = tid & 31, wid = tid >> 5;
    int wr = wid >> 2, wc = wid & 3;
    int row = tid >> 1, half = tid & 1;

    int arow = m0 + row; if (arow >= cnt) arow = cnt - 1;
    int tok  = g_tok[e * MAXP + arow];
    int brow = n0 + row;
    RowPtrs rp;
    rp.a = (const uint4*)(g_x16 + (size_t)tok * D_MODEL);
    rp.b = (const uint4*)(g_W1t + ((size_t)e * F_DIM + brow) * D_MODEL);

    uint32_t aoff[4], boff[2];
    make_offsets(wr, wc, lane, aoff, boff);

    float c[4][4][4];
#pragma unroll
    for (int i = 0; i < 4; i++)
#pragma unroll
        for (int j = 0; j < 4; j++)
#pragma unroll
            for (int k = 0; k < 4; k++) c[i][j][k] = 0.f;

    run_mainloop(smbase, rp, D_MODEL / BK, aoff, boff, c, row, half);

    // epilogue: bias + relu -> fp16 g_H16 (register-direct)
    int lrow = lane >> 2, lcol2 = (lane & 3) * 2;
#pragma unroll
    for (int nt = 0; nt < 4; nt++) {
        int col = n0 + wc * 32 + nt * 8 + lcol2;
        float bb0 = b1[e * F_DIM + col];
        float bb1 = b1[e * F_DIM + col + 1];
#pragma unroll
        for (int mt = 0; mt < 4; mt++) {
            int r0 = m0 + wr * 64 + mt * 16 + lrow;
#pragma unroll
            for (int h = 0; h < 2; h++) {
                int r = r0 + h * 8;
                if (r < cnt) {
                    float v0 = fmaxf(c[mt][nt][h * 2 + 0] + bb0, 0.f);
                    float v1 = fmaxf(c[mt][nt][h * 2 + 1] + bb1, 0.f);
                    size_t o = ((size_t)e * MAXP + r) * F_DIM + col;
                    *(__half2*)(g_H16 + o) = __floats2half2_rn(v0, v1);
                }
            }
        }
    }
}

// ---------------------------------------------------------------------------
// GEMM2: O[e-rows, D] = wt * ( H @ W2t[e] + b2[e] )
__global__ void __launch_bounds__(256, 2)
gemm2_mma(const float* __restrict__ b2) {
    extern __shared__ __align__(16) char tiles[];
    uint32_t smbase = smem_u32(tiles);
    int e   = blockIdx.z;
    int cnt = g_counts[e];
    int m0  = blockIdx.y * BM;
    if (m0 >= cnt) return;
    int n0  = blockIdx.x * BN;
    int tid = threadIdx.x, lane = tid & 31, wid = tid >> 5;
    int wr = wid >> 2, wc = wid & 3;
    int row = tid >> 1, half = tid & 1;

    int arow = m0 + row; if (arow >= cnt) arow = cnt - 1;
    int brow = n0 + row;
    RowPtrs rp;
    rp.a = (const uint4*)(g_H16 + ((size_t)e * MAXP + arow) * F_DIM);
    rp.b = (const uint4*)(g_W2t + ((size_t)e * D_MODEL + brow) * F_DIM);

    uint32_t aoff[4], boff[2];
    make_offsets(wr, wc, lane, aoff, boff);

    float c[4][4][4];
#pragma unroll
    for (int i = 0; i < 4; i++)
#pragma unroll
        for (int j = 0; j < 4; j++)
#pragma unroll
            for (int k = 0; k < 4; k++) c[i][j][k] = 0.f;

    run_mainloop(smbase, rp, F_DIM / BK, aoff, boff, c, row, half);

    // epilogue: (acc + bias) * wt -> g_O (fp32)
    int lrow = lane >> 2, lcol2 = (lane & 3) * 2;
#pragma unroll
    for (int nt = 0; nt < 4; nt++) {
        int col = n0 + wc * 32 + nt * 8 + lcol2;
        float bb0 = b2[e * D_MODEL + col];
        float bb1 = b2[e * D_MODEL + col + 1];
#pragma unroll
        for (int mt = 0; mt < 4; mt++) {
            int r0 = m0 + wr * 64 + mt * 16 + lrow;
#pragma unroll
            for (int h = 0; h < 2; h++) {
                int r = r0 + h * 8;
                if (r < cnt) {
                    float wt = g_wt[e * MAXP + r];
                    float2 o;
                    o.x = (c[mt][nt][h * 2 + 0] + bb0) * wt;
                    o.y = (c[mt][nt][h * 2 + 1] + bb1) * wt;
                    *(float2*)(g_O + ((size_t)e * MAXP + r) * D_MODEL + col) = o;
                }
            }
        }
    }
}

// ---------------------------------------------------------------------------
__global__ void ln_kernel(const float* __restrict__ x,
                          const float* __restrict__ gamma,
                          const float* __restrict__ beta,
                          float* __restrict__ out) {
    int t   = blockIdx.x;
    int tid = threadIdx.x;
    int s0 = g_slot[t * 2 + 0];
    int s1 = g_slot[t * 2 + 1];

    const float4* xr = (const float4*)(x + (size_t)t * D_MODEL);
    const float4* o0 = (const float4*)(g_O + (size_t)s0 * D_MODEL);
    const float4* o1 = (const float4*)(g_O + (size_t)s1 * D_MODEL);

    float4 xv = xr[tid];
    float4 a  = o0[tid];
    float4 b  = o1[tid];
    float4 y;
    y.x = xv.x + a.x + b.x;
    y.y = xv.y + a.y + b.y;
    y.z = xv.z + a.z + b.z;
    y.w = xv.w + a.w + b.w;

    float s  = y.x + y.y + y.z + y.w;
    float sq = y.x * y.x + y.y * y.y + y.z * y.z + y.w * y.w;
#pragma unroll
    for (int off = 16; off > 0; off >>= 1) {
        s  += __shfl_down_sync(0xffffffffu, s,  off);
        sq += __shfl_down_sync(0xffffffffu, sq, off);
    }
    int warp = tid >> 5, lane = tid & 31;
    __shared__ float ws[8], wq[8], red[2];
    if (lane == 0) { ws[warp] = s; wq[warp] = sq; }
    __syncthreads();
    if (tid == 0) {
        float ts = 0.f, tq = 0.f;
#pragma unroll
        for (int i = 0; i < 8; i++) { ts += ws[i]; tq += wq[i]; }
        red[0] = ts; red[1] = tq;
    }
    __syncthreads();

    float mu  = red[0] * (1.0f / D_MODEL);
    float var = red[1] * (1.0f / D_MODEL) - mu * mu;
    float inv = rsqrtf(var + LN_EPS);

    float4 g  = ((const float4*)gamma)[tid];
    float4 bt = ((const float4*)beta)[tid];
    float4 o;
    o.x = g.x * (y.x - mu) * inv + bt.x;
    o.y = g.y * (y.y - mu) * inv + bt.y;
    o.z = g.z * (y.z - mu) * inv + bt.z;
    o.w = g.w * (y.w - mu) * inv + bt.w;
    ((float4*)out)[(size_t)t * (D_MODEL / 4) + tid] = o;
}

// ---------------------------------------------------------------------------
extern "C" void kernel_launch(void* const* d_in, const int* in_sizes, int n_in,
                              void* d_out, int out_size) {
    const float* x     = (const float*)d_in[0];
    const float* Wg    = (const float*)d_in[1];
    const float* bg    = (const float*)d_in[2];
    const float* W1    = (const float*)d_in[3];
    const float* b1    = (const float*)d_in[4];
    const float* W2    = (const float*)d_in[5];
    const float* b2    = (const float*)d_in[6];
    const float* gamma = (const float*)d_in[7];
    const float* beta  = (const float*)d_in[8];
    float* out = (float*)d_out;

    cudaFuncSetAttribute(gemm1_mma, cudaFuncAttributeMaxDynamicSharedMemorySize, SMEM_BYTES);
    cudaFuncSetAttribute(gemm2_mma, cudaFuncAttributeMaxDynamicSharedMemorySize, SMEM_BYTES);

    init_kernel<<<1, 32>>>();
    gating_kernel<<<T_TOKENS / 8, 256>>>(x, Wg, bg);
    convert_x_kernel<<<T_TOKENS * D_MODEL / 4 / 256, 256>>>(x);
    transpose_w1_kernel<<<dim3(F_DIM / 32, D_MODEL / 64, N_EXP), dim3(32, 8)>>>(W1);
    transpose_w2_kernel<<<dim3(D_MODEL / 32, F_DIM / 64, N_EXP), dim3(32, 8)>>>(W2);

    gemm1_mma<<<dim3(F_DIM / BN, MAXP / BM, N_EXP), 256, SMEM_BYTES>>>(b1);
    gemm2_mma<<<dim3(D_MODEL / BN, MAXP / BM, N_EXP), 256, SMEM_BYTES>>>(b2);

    ln_kernel<<<T_TOKENS, 256>>>(x, gamma, beta, out);
}